// round 10
// baseline (speedup 1.0000x reference)
#include <cuda_runtime.h>
#include <math.h>
#include <stdint.h>

// ---------------- constants ----------------
#define TKN 512      // B*N tokens
#define DIM 512
#define CCH 256      // C
#define HGT 128
#define WID 128
#define PPT 36       // P
#define PGN 128
#define TOTN 66832
#define CC2 65536

// ---------------- scratch ----------------
__device__ float g_imgT[8 * HGT * WID * CCH];
__device__ float g_hidden[TKN * PGN];
__device__ float g_grid[TKN * PPT * 2];
__device__ float g_params[(size_t)TKN * TOTN];
__device__ float g_sampled[TKN * PPT * CCH];
__device__ float g_h[TKN * PPT * CCH];
__device__ float g_tok[TKN * DIM];
__device__ float g_tok2[TKN * DIM];
__device__ float g_x[TKN * DIM];
__device__ float g_qkv[TKN * 3 * DIM];
__device__ float g_attout[TKN * DIM];
__device__ float g_ff[TKN * 4 * DIM];
__device__ float r_wpg2[PGN * TOTN];
__device__ float r_wout[PPT * CCH * DIM];
__device__ float r_wqkv[DIM * 3 * DIM];
__device__ float r_wproj[DIM * DIM];
__device__ float r_wfc1[DIM * 4 * DIM];
__device__ float r_wfc2[4 * DIM * DIM];

__device__ __forceinline__ float gelu_f(float x) {
    return 0.5f * x * (1.0f + erff(x * 0.70710678118654752440f));
}
__device__ __forceinline__ float f2tf32f(float x) {
    uint32_t r;
    asm("cvt.rna.tf32.f32 %0, %1;" : "=r"(r) : "f"(x));
    return __uint_as_float(r);
}
__device__ __forceinline__ void red2f(float* p, float a, float b) {
    asm volatile("red.global.add.v2.f32 [%0], {%1, %2};"
                 :: "l"(p), "f"(a), "f"(b) : "memory");
}

// ---------------- wpg2 rounding ----------------
#define N4_0 2138624
__global__ void round_pg2_k(const float* __restrict__ w0) {
    int i = blockIdx.x * 256 + threadIdx.x;
    if (i >= N4_0) return;
    float4 v = ((const float4*)w0)[i];
    v.x = f2tf32f(v.x); v.y = f2tf32f(v.y);
    v.z = f2tf32f(v.z); v.w = f2tf32f(v.w);
    ((float4*)r_wpg2)[i] = v;
}

// ---------------- remaining 5 weights ----------------
#define N4_1 1179648
#define N4_2 196608
#define N4_3 65536
#define N4_4 262144
#define N4_5 262144
#define R4_2 (N4_1)
#define R4_3 (R4_2 + N4_2)
#define R4_4 (R4_3 + N4_3)
#define R4_5 (R4_4 + N4_4)
#define R4_T (R4_5 + N4_5)
__global__ void round_rest_k(const float* __restrict__ w1, const float* __restrict__ w2,
                             const float* __restrict__ w3, const float* __restrict__ w4,
                             const float* __restrict__ w5) {
    int i = blockIdx.x * 256 + threadIdx.x;
    if (i >= R4_T) return;
    const float* src; float* dst; int off;
    if      (i < R4_2) { src = w1; dst = r_wout;  off = i; }
    else if (i < R4_3) { src = w2; dst = r_wqkv;  off = i - R4_2; }
    else if (i < R4_4) { src = w3; dst = r_wproj; off = i - R4_3; }
    else if (i < R4_5) { src = w4; dst = r_wfc1;  off = i - R4_4; }
    else               { src = w5; dst = r_wfc2;  off = i - R4_5; }
    float4 v = ((const float4*)src)[off];
    v.x = f2tf32f(v.x); v.y = f2tf32f(v.y);
    v.z = f2tf32f(v.z); v.w = f2tf32f(v.w);
    ((float4*)dst)[off] = v;
}

// ---------------- img transpose ----------------
__global__ void transpose_k(const float* __restrict__ in) {
    __shared__ float tile[32][33];
    int b = blockIdx.z;
    int s0 = blockIdx.x * 32;
    int c0 = blockIdx.y * 32;
    const float* ib = in + (size_t)b * CCH * HGT * WID;
    float* ob = g_imgT + (size_t)b * HGT * WID * CCH;
    int tid = threadIdx.x;
    {
        int c = tid >> 3, s4 = tid & 7;
        float4 v = *(const float4*)(ib + (size_t)(c0 + c) * (HGT * WID) + s0 + 4 * s4);
        tile[4 * s4 + 0][c] = v.x;
        tile[4 * s4 + 1][c] = v.y;
        tile[4 * s4 + 2][c] = v.z;
        tile[4 * s4 + 3][c] = v.w;
    }
    __syncthreads();
    {
        int g = tid & 7, s = tid >> 3;
        float4 v;
        v.x = tile[s][4 * g + 0];
        v.y = tile[s][4 * g + 1];
        v.z = tile[s][4 * g + 2];
        v.w = tile[s][4 * g + 3];
        *(float4*)(ob + (size_t)(s0 + s) * CCH + c0 + 4 * g) = v;
    }
}

// ---------------- per-token pre ----------------
__global__ void pre_k(const float* __restrict__ x, const float* __restrict__ roi,
                      const float* __restrict__ g_off, const float* __restrict__ b_off,
                      const float* __restrict__ w_off, const float* __restrict__ off_bias,
                      const float* __restrict__ g_pg, const float* __restrict__ b_pg,
                      const float* __restrict__ w_pg1, const float* __restrict__ b_pg1) {
    int t = blockIdx.x;
    int tid = threadIdx.x;
    __shared__ float xoff[DIM], xpg[DIM], offs[72];
    __shared__ float rs[4], rs2[4], stats[4];

    const float* xr = x + (size_t)t * DIM;
    float v[4], s = 0.f, s2 = 0.f;
#pragma unroll
    for (int i = 0; i < 4; i++) { v[i] = xr[tid + 128 * i]; s += v[i]; s2 += v[i] * v[i]; }
#pragma unroll
    for (int o = 16; o; o >>= 1) {
        s  += __shfl_down_sync(0xffffffffu, s,  o);
        s2 += __shfl_down_sync(0xffffffffu, s2, o);
    }
    if ((tid & 31) == 0) { rs[tid >> 5] = s; rs2[tid >> 5] = s2; }
    __syncthreads();
    float ts = rs[0] + rs[1] + rs[2] + rs[3];
    float ts2 = rs2[0] + rs2[1] + rs2[2] + rs2[3];
    float mean = ts * (1.f / DIM);
    float var = ts2 * (1.f / DIM) - mean * mean;
    float rstd = rsqrtf(var + 1e-5f);
#pragma unroll
    for (int i = 0; i < 4; i++) {
        int k = tid + 128 * i;
        float xn = (v[i] - mean) * rstd;
        xoff[k] = xn * g_off[k] + b_off[k];
        xpg[k]  = xn * g_pg[k]  + b_pg[k];
    }
    __syncthreads();

    {
        float h = b_pg1[tid];
        for (int k = 0; k < DIM; k++) h = fmaf(xpg[k], w_pg1[k * PGN + tid], h);
        g_hidden[t * PGN + tid] = f2tf32f(h);
    }
    if (tid < 72) {
        float o = off_bias[tid];
        for (int k = 0; k < DIM; k++) o = fmaf(xoff[k], w_off[k * 72 + tid], o);
        offs[tid] = o;
    }
    __syncthreads();
    if (tid < 2) {
        float mu = 0.f;
        for (int p = 0; p < PPT; p++) mu += offs[p * 2 + tid];
        mu *= (1.f / PPT);
        float vv = 0.f;
        for (int p = 0; p < PPT; p++) { float d = offs[p * 2 + tid] - mu; vv += d * d; }
        vv *= (1.f / (PPT - 1));
        stats[tid * 2] = mu;
        stats[tid * 2 + 1] = sqrtf(vv) + 1e-5f;
    }
    __syncthreads();
    if (tid < 72) {
        int coord = tid & 1, p = tid >> 1;
        float mu = stats[coord * 2], sd = stats[coord * 2 + 1];
        float on = (offs[tid] - mu) / (3.f * sd);
        float tl = roi[t * 4 + coord], br = roi[t * 4 + 2 + coord];
        float xy = 0.5f * (tl + br), wh = br - tl;
        float pt = xy + on * wh;
        g_grid[(t * PPT + p) * 2 + coord] = pt * 2.f - 1.f;
    }
}

// ---------------- bilinear grid sample ----------------
__global__ void sample_k() {
    int p = blockIdx.x, t = blockIdx.y;
    int c4 = threadIdx.x << 2;
    int b = t >> 6;
    float gx = g_grid[(t * PPT + p) * 2 + 0];
    float gy = g_grid[(t * PPT + p) * 2 + 1];
    float x = ((gx + 1.f) * WID - 1.f) * 0.5f;
    float y = ((gy + 1.f) * HGT - 1.f) * 0.5f;
    float x0f = floorf(x), y0f = floorf(y);
    float wx = x - x0f, wy = y - y0f;
    int x0 = min(max((int)x0f, 0), WID - 1);
    int x1 = min(max((int)x0f + 1, 0), WID - 1);
    int y0 = min(max((int)y0f, 0), HGT - 1);
    int y1 = min(max((int)y0f + 1, 0), HGT - 1);
    const float* ib = g_imgT + (size_t)b * HGT * WID * CCH;
    float4 v00 = *(const float4*)(ib + (size_t)(y0 * WID + x0) * CCH + c4);
    float4 v01 = *(const float4*)(ib + (size_t)(y0 * WID + x1) * CCH + c4);
    float4 v10 = *(const float4*)(ib + (size_t)(y1 * WID + x0) * CCH + c4);
    float4 v11 = *(const float4*)(ib + (size_t)(y1 * WID + x1) * CCH + c4);
    float w00 = (1.f - wx) * (1.f - wy), w01 = wx * (1.f - wy);
    float w10 = (1.f - wx) * wy,         w11 = wx * wy;
    float4 o;
    o.x = v00.x * w00 + v01.x * w01 + v10.x * w10 + v11.x * w11;
    o.y = v00.y * w00 + v01.y * w01 + v10.y * w10 + v11.y * w11;
    o.z = v00.z * w00 + v01.z * w01 + v10.z * w10 + v11.z * w11;
    o.w = v00.w * w00 + v01.w * w01 + v10.w * w10 + v11.w * w11;
    *(float4*)(g_sampled + ((size_t)t * PPT + p) * CCH + c4) = o;
}

// ---------------- cp.async helpers ----------------
__device__ __forceinline__ void cpa16(uint32_t dst, const void* src, bool pred) {
    int sz = pred ? 16 : 0;
    asm volatile("cp.async.cg.shared.global [%0], [%1], 16, %2;"
                 :: "r"(dst), "l"(src), "r"(sz));
}
__device__ __forceinline__ void cpa_commit() {
    asm volatile("cp.async.commit_group;");
}
__device__ __forceinline__ uint32_t smem_u32(const void* p) {
    uint32_t a;
    asm("{ .reg .u64 t; cvta.to.shared.u64 t, %1; cvt.u32.u64 %0, t; }" : "=r"(a) : "l"(p));
    return a;
}

// ---------------- templated tf32 GEMM with row offset m0 ----------------
#define ASZ 4608
template <int TN>
__global__ void __launch_bounds__(256)
mma_gemm_t(const float* __restrict__ A, const float* __restrict__ Bm,
           const float* __restrict__ bias, float* __restrict__ C,
           int M, int N, int K, int rnd, int act, int m0) {
    constexpr int BN   = TN * 16;
    constexpr int BSTR = BN + 8;
    constexpr int BSZf = 32 * BSTR;
    constexpr int STGf = ASZ + BSZf;
    constexpr int BIT  = BN / 32;
    constexpr int BQ   = BN / 4;

    extern __shared__ float smf[];
    uint32_t sbase = smem_u32(smf);

    int tid = threadIdx.x;
    int warp = tid >> 5, lane = tid & 31;
    int wr = (warp >> 1) * 32;
    int wc = (warp & 1) * (TN * 8);
    int bR = m0 + blockIdx.y * 128, bC = blockIdx.x * BN;
    int nz = gridDim.z;
    int Kc = K / nz;
    int kbeg = blockIdx.z * Kc;
    int ntiles = Kc >> 5;

    float acc[2][TN][4];
#pragma unroll
    for (int a = 0; a < 2; a++)
#pragma unroll
        for (int b = 0; b < TN; b++)
#pragma unroll
            for (int c = 0; c < 4; c++) acc[a][b][c] = 0.f;

    int ar[4], ac[4];
#pragma unroll
    for (int i = 0; i < 4; i++) {
        int f = tid + (i << 8);
        ar[i] = f >> 3;  ac[i] = (f & 7) << 2;
    }
    int br_[BIT], bc_[BIT];
#pragma unroll
    for (int i = 0; i < BIT; i++) {
        int f = tid + (i << 8);
        br_[i] = f / BQ; bc_[i] = (f % BQ) << 2;
    }

    auto issue = [&](int t, int stage) {
        int k0 = kbeg + (t << 5);
        uint32_t sa = sbase + stage * (STGf * 4);
#pragma unroll
        for (int i = 0; i < 4; i++) {
            cpa16(sa + (ar[i] * 36 + ac[i]) * 4,
                  A + (size_t)(bR + ar[i]) * K + k0 + ac[i], true);
        }
        uint32_t sb = sa + ASZ * 4;
#pragma unroll
        for (int i = 0; i < BIT; i++) {
            int gc = bC + bc_[i];
            cpa16(sb + (br_[i] * BSTR + bc_[i]) * 4,
                  Bm + (size_t)(k0 + br_[i]) * N + gc, gc < N);
        }
        cpa_commit();
    };

    issue(0, 0);
    for (int t = 0; t < ntiles; t++) {
        if (t + 1 < ntiles) {
            issue(t + 1, (t + 1) & 1);
            asm volatile("cp.async.wait_group 1;");
        } else {
            asm volatile("cp.async.wait_group 0;");
        }
        __syncthreads();
        const uint32_t* As = (const uint32_t*)(smf + (t & 1) * STGf);
        const uint32_t* Bs = As + ASZ;
#pragma unroll
        for (int k8 = 0; k8 < 4; k8++) {
            int kk = k8 << 3;
            uint32_t afr[2][4];
#pragma unroll
            for (int tm = 0; tm < 2; tm++) {
                int r = wr + tm * 16 + (lane >> 2);
                int c = kk + (lane & 3);
                afr[tm][0] = As[r * 36 + c];
                afr[tm][1] = As[(r + 8) * 36 + c];
                afr[tm][2] = As[r * 36 + c + 4];
                afr[tm][3] = As[(r + 8) * 36 + c + 4];
            }
#pragma unroll
            for (int tn = 0; tn < TN; tn++) {
                int col = wc + tn * 8 + (lane >> 2);
                uint32_t b0 = Bs[(kk + (lane & 3)) * BSTR + col];
                uint32_t b1 = Bs[(kk + (lane & 3) + 4) * BSTR + col];
#pragma unroll
                for (int tm = 0; tm < 2; tm++) {
                    asm volatile(
                        "mma.sync.aligned.m16n8k8.row.col.f32.tf32.tf32.f32 "
                        "{%0,%1,%2,%3}, {%4,%5,%6,%7}, {%8,%9}, {%0,%1,%2,%3};"
                        : "+f"(acc[tm][tn][0]), "+f"(acc[tm][tn][1]),
                          "+f"(acc[tm][tn][2]), "+f"(acc[tm][tn][3])
                        : "r"(afr[tm][0]), "r"(afr[tm][1]),
                          "r"(afr[tm][2]), "r"(afr[tm][3]),
                          "r"(b0), "r"(b1));
                }
            }
        }
        __syncthreads();
    }

    if (nz == 1) {
#pragma unroll
        for (int tm = 0; tm < 2; tm++) {
            int row = bR + wr + tm * 16 + (lane >> 2);
#pragma unroll
            for (int tn = 0; tn < TN; tn++) {
                int col = bC + wc + tn * 8 + ((lane & 3) << 1);
                float bv0 = 0.f, bv1 = 0.f;
                if (bias) {
                    if (col < N) bv0 = bias[col];
                    if (col + 1 < N) bv1 = bias[col + 1];
                }
                float o0 = acc[tm][tn][0] + bv0, o1 = acc[tm][tn][1] + bv1;
                float o2 = acc[tm][tn][2] + bv0, o3 = acc[tm][tn][3] + bv1;
                if (act) {
                    o0 = gelu_f(o0); o1 = gelu_f(o1);
                    o2 = gelu_f(o2); o3 = gelu_f(o3);
                }
                if (rnd | act) {
                    o0 = f2tf32f(o0); o1 = f2tf32f(o1);
                    o2 = f2tf32f(o2); o3 = f2tf32f(o3);
                }
                if (col < N) {
                    C[(size_t)row * N + col] = o0;
                    C[(size_t)(row + 8) * N + col] = o2;
                }
                if (col + 1 < N) {
                    C[(size_t)row * N + col + 1] = o1;
                    C[(size_t)(row + 8) * N + col + 1] = o3;
                }
            }
        }
    } else {
#pragma unroll
        for (int tm = 0; tm < 2; tm++) {
            int row = bR + wr + tm * 16 + (lane >> 2);
#pragma unroll
            for (int tn = 0; tn < TN; tn++) {
                int col = bC + wc + tn * 8 + ((lane & 3) << 1);
                red2f(&C[(size_t)row * N + col], acc[tm][tn][0], acc[tm][tn][1]);
                red2f(&C[(size_t)(row + 8) * N + col], acc[tm][tn][2], acc[tm][tn][3]);
            }
        }
    }
}

// ---------------- init ----------------
__global__ void init_k(const float* __restrict__ resid, const float* __restrict__ bias,
                       float* __restrict__ C, int n, int N) {
    int i = blockIdx.x * 256 + threadIdx.x;
    if (i < n) {
        int col = i % N;
        C[i] = (resid ? resid[i] : 0.f) + bias[col];
    }
}

// ---------------- tensor-core per-token mixing (token offset t0) ----------------
#define MIX_ASTR 260
#define MIX_BSTR 264
#define MIX_AF (48 * MIX_ASTR)
#define MIX_BF (32 * MIX_BSTR)
#define MIX_SMF (MIX_AF + 2 * MIX_BF + 1296)
__global__ void __launch_bounds__(256)
mixmma_k(const float* __restrict__ mb, const float* __restrict__ sb, int t0) {
    extern __shared__ float smf[];
    float* Aa  = smf;
    float* Bb  = smf + MIX_AF;
    float* sms = smf + MIX_AF + 2 * MIX_BF;
    uint32_t sbase = smem_u32(smf);

    int t = t0 + blockIdx.x, tid = threadIdx.x;
    int warp = tid >> 5, lane = tid & 31;
    const float* pt = g_params + (size_t)t * TOTN;

    for (int i = tid; i < 12 * MIX_ASTR; i += 256) Aa[36 * MIX_ASTR + i] = 0.f;
    const float4* sp4 = (const float4*)(g_sampled + (size_t)t * (PPT * CCH));
    for (int i = tid; i < PPT * CCH / 4; i += 256) {
        float4 v = sp4[i];
        int r = i >> 6, c = (i & 63) << 2;
        float* d = Aa + r * MIX_ASTR + c;
        d[0] = f2tf32f(v.x); d[1] = f2tf32f(v.y);
        d[2] = f2tf32f(v.z); d[3] = f2tf32f(v.w);
    }
    for (int i = tid; i < PPT * PPT; i += 256) sms[i] = pt[CC2 + i];

    uint32_t bB = sbase + MIX_AF * 4;
    auto issue = [&](int ch, int stg) {
        const float* src = pt + ch * 32 * 256;
        uint32_t dst = bB + stg * (MIX_BF * 4);
#pragma unroll
        for (int i = 0; i < 8; i++) {
            int e = tid + (i << 8);
            int r = e >> 6, c4 = (e & 63) << 2;
            cpa16(dst + (r * MIX_BSTR + c4) * 4, src + r * 256 + c4, true);
        }
        cpa_commit();
    };

    float acc[3][4][4];
#pragma unroll
    for (int a = 0; a < 3; a++)
#pragma unroll
        for (int b = 0; b < 4; b++)
#pragma unroll
            for (int c = 0; c < 4; c++) acc[a][b][c] = 0.f;

    issue(0, 0);
    for (int ch = 0; ch < 8; ch++) {
        if (ch + 1 < 8) {
            issue(ch + 1, (ch + 1) & 1);
            asm volatile("cp.async.wait_group 1;");
        } else {
            asm volatile("cp.async.wait_group 0;");
        }
        __syncthreads();
        const uint32_t* As = (const uint32_t*)Aa;
        const uint32_t* Bs = (const uint32_t*)(Bb + (ch & 1) * MIX_BF);
#pragma unroll
        for (int k8 = 0; k8 < 4; k8++) {
            int kk = (ch << 5) + (k8 << 3);
            int kb = k8 << 3;
            uint32_t afr[3][4];
#pragma unroll
            for (int mt = 0; mt < 3; mt++) {
                int r = mt * 16 + (lane >> 2);
                int c = kk + (lane & 3);
                afr[mt][0] = As[r * MIX_ASTR + c];
                afr[mt][1] = As[(r + 8) * MIX_ASTR + c];
                afr[mt][2] = As[r * MIX_ASTR + c + 4];
                afr[mt][3] = As[(r + 8) * MIX_ASTR + c + 4];
            }
#pragma unroll
            for (int tn = 0; tn < 4; tn++) {
                int col = warp * 32 + tn * 8 + (lane >> 2);
                uint32_t b0 = Bs[(kb + (lane & 3)) * MIX_BSTR + col];
                uint32_t b1 = Bs[(kb + (lane & 3) + 4) * MIX_BSTR + col];
#pragma unroll
                for (int mt = 0; mt < 3; mt++) {
                    asm volatile(
                        "mma.sync.aligned.m16n8k8.row.col.f32.tf32.tf32.f32 "
                        "{%0,%1,%2,%3}, {%4,%5,%6,%7}, {%8,%9}, {%0,%1,%2,%3};"
                        : "+f"(acc[mt][tn][0]), "+f"(acc[mt][tn][1]),
                          "+f"(acc[mt][tn][2]), "+f"(acc[mt][tn][3])
                        : "r"(afr[mt][0]), "r"(afr[mt][1]),
                          "r"(afr[mt][2]), "r"(afr[mt][3]),
                          "r"(b0), "r"(b1));
                }
            }
        }
        __syncthreads();
    }

    float* hsh = Bb;
#pragma unroll
    for (int mt = 0; mt < 3; mt++) {
#pragma unroll
        for (int half = 0; half < 2; half++) {
            int row = mt * 16 + (lane >> 2) + half * 8;
            if (row >= PPT) continue;
#pragma unroll
            for (int tn = 0; tn < 4; tn++) {
                int col = warp * 32 + tn * 8 + ((lane & 3) << 1);
                hsh[row * 260 + col]     = gelu_f(acc[mt][tn][half * 2 + 0] + mb[col]);
                hsh[row * 260 + col + 1] = gelu_f(acc[mt][tn][half * 2 + 1] + mb[col + 1]);
            }
        }
    }
    __syncthreads();

    int d4 = tid & 63;
    int q0 = (tid >> 6) * 9;
    float4 accq[9];
#pragma unroll
    for (int q = 0; q < 9; q++) {
        float s = sb[q0 + q];
        accq[q] = make_float4(s, s, s, s);
    }
    for (int p = 0; p < PPT; p++) {
        float4 hv = *(const float4*)(hsh + p * 260 + 4 * d4);
#pragma unroll
        for (int q = 0; q < 9; q++) {
            float smv = sms[(q0 + q) * PPT + p];
            accq[q].x = fmaf(smv, hv.x, accq[q].x);
            accq[q].y = fmaf(smv, hv.y, accq[q].y);
            accq[q].z = fmaf(smv, hv.z, accq[q].z);
            accq[q].w = fmaf(smv, hv.w, accq[q].w);
        }
    }
    float* ho = g_h + (size_t)t * (PPT * CCH);
#pragma unroll
    for (int q = 0; q < 9; q++) {
        float4 o;
        o.x = f2tf32f(gelu_f(accq[q].x));
        o.y = f2tf32f(gelu_f(accq[q].y));
        o.z = f2tf32f(gelu_f(accq[q].z));
        o.w = f2tf32f(gelu_f(accq[q].w));
        *(float4*)(ho + (q0 + q) * CCH + 4 * d4) = o;
    }
}

// ---------------- layernorm ----------------
__global__ void ln_k(const float* __restrict__ x, const float* __restrict__ g,
                     const float* __restrict__ bb, float* __restrict__ y) {
    int t = blockIdx.x, tid = threadIdx.x;
    __shared__ float rs[4], rs2[4];
    const float* xr = x + (size_t)t * DIM;
    float v[4], s = 0.f, s2 = 0.f;
#pragma unroll
    for (int i = 0; i < 4; i++) { v[i] = xr[tid + 128 * i]; s += v[i]; s2 += v[i] * v[i]; }
#pragma unroll
    for (int o = 16; o; o >>= 1) {
        s  += __shfl_down_sync(0xffffffffu, s,  o);
        s2 += __shfl_down_sync(0xffffffffu, s2, o);
    }
    if ((tid & 31) == 0) { rs[tid >> 5] = s; rs2[tid >> 5] = s2; }
    __syncthreads();
    float ts = rs[0] + rs[1] + rs[2] + rs[3];
    float ts2 = rs2[0] + rs2[1] + rs2[2] + rs2[3];
    float mean = ts * (1.f / DIM);
    float var = ts2 * (1.f / DIM) - mean * mean;
    float rstd = rsqrtf(var + 1e-5f);
#pragma unroll
    for (int i = 0; i < 4; i++) {
        int k = tid + 128 * i;
        y[(size_t)t * DIM + k] = f2tf32f((v[i] - mean) * rstd * g[k] + bb[k]);
    }
}

// ---------------- attention ----------------
__global__ void attn_k() {
    int b = blockIdx.x, h = blockIdx.y;
    int q = threadIdx.x;
    __shared__ float Ks[64 * 64], Vs[64 * 64];
    const float* base = g_qkv + (size_t)b * 64 * (3 * DIM);
    for (int i = q; i < 64 * 64; i += 64) {
        int n = i >> 6, d2 = i & 63;
        Ks[i] = base[(size_t)n * (3 * DIM) + DIM     + h * 64 + d2];
        Vs[i] = base[(size_t)n * (3 * DIM) + 2 * DIM + h * 64 + d2];
    }
    float qreg[64];
    const float* qrow = base + (size_t)q * (3 * DIM) + h * 64;
#pragma unroll
    for (int d2 = 0; d2 < 64; d2++) qreg[d2] = qrow[d2];
    __syncthreads();

    float sc[64];
#pragma unroll
    for (int k = 0; k < 64; k++) {
        float s = 0.f;
#pragma unroll
        for (int d2 = 0; d2 < 64; d2++) s = fmaf(qreg[d2], Ks[k * 64 + d2], s);
        sc[k] = s * 0.125f;
    }
    float mx = sc[0];
#pragma unroll
    for (int k = 1; k < 64; k++) mx = fmaxf(mx, sc[k]);
    float sum = 0.f;
#pragma unroll
    for (int k = 0; k < 64; k++) { sc[k] = expf(sc[k] - mx); sum += sc[k]; }
    float inv = 1.f / sum;
#pragma unroll
    for (int k = 0; k < 64; k++) sc[k] *= inv;

    float* orow = g_attout + (size_t)(b * 64 + q) * DIM + h * 64;
    for (int d2 = 0; d2 < 64; d2++) {
        float o = 0.f;
#pragma unroll
        for (int k = 0; k < 64; k++) o = fmaf(sc[k], Vs[k * 64 + d2], o);
        orow[d2] = f2tf32f(o);
    }
}

// ---------------- streams / events ----------------
#define DSM8 (2 * (ASZ + 32 * 136) * 4)
#define DSM4 (2 * (ASZ + 32 * 72) * 4)
struct SfStreams {
    cudaStream_t s1, s2;
    cudaEvent_t e_root, e_pre, e_rpg2, e_inits, e_sample,
                e_p0, e_m0, e_m1, e_wout, e_t2, e_proj, e_outi;
    SfStreams() {
        cudaStreamCreateWithFlags(&s1, cudaStreamNonBlocking);
        cudaStreamCreateWithFlags(&s2, cudaStreamNonBlocking);
        cudaEventCreateWithFlags(&e_root,   cudaEventDisableTiming);
        cudaEventCreateWithFlags(&e_pre,    cudaEventDisableTiming);
        cudaEventCreateWithFlags(&e_rpg2,   cudaEventDisableTiming);
        cudaEventCreateWithFlags(&e_inits,  cudaEventDisableTiming);
        cudaEventCreateWithFlags(&e_sample, cudaEventDisableTiming);
        cudaEventCreateWithFlags(&e_p0,     cudaEventDisableTiming);
        cudaEventCreateWithFlags(&e_m0,     cudaEventDisableTiming);
        cudaEventCreateWithFlags(&e_m1,     cudaEventDisableTiming);
        cudaEventCreateWithFlags(&e_wout,   cudaEventDisableTiming);
        cudaEventCreateWithFlags(&e_t2,     cudaEventDisableTiming);
        cudaEventCreateWithFlags(&e_proj,   cudaEventDisableTiming);
        cudaEventCreateWithFlags(&e_outi,   cudaEventDisableTiming);
        cudaFuncSetAttribute(mma_gemm_t<8>, cudaFuncAttributeMaxDynamicSharedMemorySize, DSM8);
        cudaFuncSetAttribute(mma_gemm_t<4>, cudaFuncAttributeMaxDynamicSharedMemorySize, DSM4);
        cudaFuncSetAttribute(mixmma_k, cudaFuncAttributeMaxDynamicSharedMemorySize,
                             MIX_SMF * 4);
    }
};
static SfStreams g_sf;

// ---------------- launch ----------------
extern "C" void kernel_launch(void* const* d_in, const int* in_sizes, int n_in,
                              void* d_out, int out_size) {
    const float* token_embed = (const float*)d_in[0];
    const float* token_roi   = (const float*)d_in[1];
    const float* img_feat    = (const float*)d_in[2];
    const float* ln_off_g    = (const float*)d_in[3];
    const float* ln_off_b    = (const float*)d_in[4];
    const float* w_off       = (const float*)d_in[5];
    const float* off_bias    = (const float*)d_in[6];
    const float* ln_pg_g     = (const float*)d_in[7];
    const float* ln_pg_b     = (const float*)d_in[8];
    const float* w_pg1       = (const float*)d_in[9];
    const float* b_pg1       = (const float*)d_in[10];
    const float* w_pg2       = (const float*)d_in[11];
    const float* b_pg2       = (const float*)d_in[12];
    const float* m_beta      = (const float*)d_in[13];
    const float* s_beta      = (const float*)d_in[14];
    const float* w_out       = (const float*)d_in[15];
    const float* b_out       = (const float*)d_in[16];
    const float* ln1_g       = (const float*)d_in[17];
    const float* ln1_b       = (const float*)d_in[18];
    const float* w_qkv       = (const float*)d_in[19];
    const float* b_qkv       = (const float*)d_in[20];
    const float* w_proj      = (const float*)d_in[21];
    const float* b_proj      = (const float*)d_in[22];
    const float* ln2_g       = (const float*)d_in[23];
    const float* ln2_b       = (const float*)d_in[24];
    const float* w_fc1       = (const float*)d_in[25];
    const float* b_fc1       = (const float*)d_in[26];
    const float* w_fc2       = (const float*)d_in[27];
    const float* b_fc2       = (const float*)d_in[28];
    float* out = (float*)d_out;

    void* p;
    cudaGetSymbolAddress(&p, g_hidden);  float* hidden = (float*)p;
    cudaGetSymbolAddress(&p, g_params);  float* params = (float*)p;
    cudaGetSymbolAddress(&p, g_h);       float* hbuf   = (float*)p;
    cudaGetSymbolAddress(&p, g_tok);     float* tok    = (float*)p;
    cudaGetSymbolAddress(&p, g_tok2);    float* tok2   = (float*)p;
    cudaGetSymbolAddress(&p, g_x);       float* xbuf   = (float*)p;
    cudaGetSymbolAddress(&p, g_qkv);     float* qkv    = (float*)p;
    cudaGetSymbolAddress(&p, g_attout);  float* attout = (float*)p;
    cudaGetSymbolAddress(&p, g_ff);      float* ff     = (float*)p;
    cudaGetSymbolAddress(&p, r_wpg2);    float* rwpg2  = (float*)p;
    cudaGetSymbolAddress(&p, r_wout);    float* rwout  = (float*)p;
    cudaGetSymbolAddress(&p, r_wqkv);    float* rwqkv  = (float*)p;
    cudaGetSymbolAddress(&p, r_wproj);   float* rwproj = (float*)p;
    cudaGetSymbolAddress(&p, r_wfc1);    float* rwfc1  = (float*)p;
    cudaGetSymbolAddress(&p, r_wfc2);    float* rwfc2  = (float*)p;

    const int DSMX = MIX_SMF * 4;
    cudaStream_t s0 = 0, s1 = g_sf.s1, s2 = g_sf.s2;

    // ---- fork ----
    cudaEventRecord(g_sf.e_root, s0);
    cudaStreamWaitEvent(s1, g_sf.e_root, 0);
    cudaStreamWaitEvent(s2, g_sf.e_root, 0);

    // s0: pre_k
    pre_k<<<TKN, 128, 0, s0>>>(token_embed, token_roi, ln_off_g, ln_off_b, w_off, off_bias,
                               ln_pg_g, ln_pg_b, w_pg1, b_pg1);
    cudaEventRecord(g_sf.e_pre, s0);

    // s1: wpg2 rounding, then rest + inits
    round_pg2_k<<<(N4_0 + 255) / 256, 256, 0, s1>>>(w_pg2);
    cudaEventRecord(g_sf.e_rpg2, s1);
    round_rest_k<<<(R4_T + 255) / 256, 256, 0, s1>>>(w_out, w_qkv, w_proj, w_fc1, w_fc2);
    init_k<<<(TKN * DIM + 255) / 256, 256, 0, s1>>>(token_embed, b_out, tok, TKN * DIM, DIM);
    init_k<<<(TKN * 3 * DIM + 255) / 256, 256, 0, s1>>>(nullptr, b_qkv, qkv, TKN * 3 * DIM, 3 * DIM);
    cudaEventRecord(g_sf.e_inits, s1);

    // s2: transpose, then sampling
    transpose_k<<<dim3((HGT * WID) / 32, CCH / 32, 8), 256, 0, s2>>>(img_feat);
    cudaStreamWaitEvent(s2, g_sf.e_pre, 0);
    sample_k<<<dim3(PPT, TKN), 64, 0, s2>>>();
    cudaEventRecord(g_sf.e_sample, s2);

    // s0: params GEMM, token halves (TN=8)
    cudaStreamWaitEvent(s0, g_sf.e_rpg2, 0);
    mma_gemm_t<8><<<dim3((TOTN + 127) / 128, 2, 1), 256, DSM8, s0>>>(
        hidden, rwpg2, b_pg2, params, TKN, TOTN, PGN, 1, 0, 0);
    cudaEventRecord(g_sf.e_p0, s0);
    mma_gemm_t<8><<<dim3((TOTN + 127) / 128, 2, 1), 256, DSM8, s0>>>(
        hidden, rwpg2, b_pg2, params, TKN, TOTN, PGN, 1, 0, 256);

    // s2: mix half0 (needs params h0 + sampled), overlaps params h1
    cudaStreamWaitEvent(s2, g_sf.e_p0, 0);
    mixmma_k<<<256, 256, DSMX, s2>>>(m_beta, s_beta, 0);
    cudaEventRecord(g_sf.e_m0, s2);
    // s2: mix half1 (params h1 done when s0 finishes; enforced below via s2 wait)
    // note: s0's params_h1 completion is ordered before e_m1 consumers via explicit event:
    // record an event on s0 after params_h1 and make s2 wait on it.
    // (event e_wout reused later; use dedicated ordering here)
    // -- we record e_outi? no; create order: s2 waits on s0's params_h1 through e_m1 path:
    // simplest: record event on s0 now.
    cudaEventRecord(g_sf.e_t2, s0);              // params_h1 done marker
    cudaStreamWaitEvent(s2, g_sf.e_t2, 0);
    mixmma_k<<<256, 256, DSMX, s2>>>(m_beta, s_beta, 256);
    cudaEventRecord(g_sf.e_m1, s2);

    // s0: w_out half0 (needs h rows 0..255 + init_tok), overlaps mix half1
    cudaStreamWaitEvent(s0, g_sf.e_m0, 0);
    cudaStreamWaitEvent(s0, g_sf.e_inits, 0);
    mma_gemm_t<4><<<dim3(DIM / 64, 2, 16), 256, DSM4, s0>>>(
        hbuf, rwout, nullptr, tok, TKN, DIM, PPT * CCH, 0, 0, 0);
    // s0: w_out half1
    cudaStreamWaitEvent(s0, g_sf.e_m1, 0);
    mma_gemm_t<4><<<dim3(DIM / 64, 2, 16), 256, DSM4, s0>>>(
        hbuf, rwout, nullptr, tok, TKN, DIM, PPT * CCH, 0, 0, 256);
    cudaEventRecord(g_sf.e_wout, s0);

    // s1: init_tok2 in parallel
    cudaStreamWaitEvent(s1, g_sf.e_wout, 0);
    init_k<<<(TKN * DIM + 255) / 256, 256, 0, s1>>>(tok, b_proj, tok2, TKN * DIM, DIM);
    cudaEventRecord(g_sf.e_p0, s1);   // reuse as tok2-ready marker

    // s0: LN1 -> qkv -> attention
    ln_k<<<TKN, 128, 0, s0>>>(tok, ln1_g, ln1_b, xbuf);
    mma_gemm_t<4><<<dim3((3 * DIM) / 64, TKN / 128, 4), 256, DSM4, s0>>>(
        xbuf, rwqkv, nullptr, qkv, TKN, 3 * DIM, DIM, 0, 0, 0);
    attn_k<<<dim3(8, 8), 64, 0, s0>>>();
    // s0: proj
    cudaStreamWaitEvent(s0, g_sf.e_p0, 0);
    mma_gemm_t<4><<<dim3(DIM / 64, TKN / 128, 8), 256, DSM4, s0>>>(
        attout, rwproj, nullptr, tok2, TKN, DIM, DIM, 0, 0, 0);
    cudaEventRecord(g_sf.e_proj, s0);

    // s2: init_out in parallel
    cudaStreamWaitEvent(s2, g_sf.e_proj, 0);
    init_k<<<(TKN * DIM + 255) / 256, 256, 0, s2>>>(tok2, b_fc2, out, TKN * DIM, DIM);
    cudaEventRecord(g_sf.e_outi, s2);

    // s0: LN2 -> fc1 (fused bias+gelu) -> fc2
    ln_k<<<TKN, 128, 0, s0>>>(tok2, ln2_g, ln2_b, xbuf);
    mma_gemm_t<4><<<dim3((4 * DIM) / 64, TKN / 128, 1), 256, DSM4, s0>>>(
        xbuf, rwfc1, b_fc1, ff, TKN, 4 * DIM, DIM, 0, 1, 0);
    cudaStreamWaitEvent(s0, g_sf.e_outi, 0);
    mma_gemm_t<4><<<dim3(DIM / 64, TKN / 128, 16), 256, DSM4, s0>>>(
        ff, rwfc2, nullptr, out, TKN, DIM, 4 * DIM, 0, 0, 0);
}

// round 11
// speedup vs baseline: 1.0629x; 1.0629x over previous
#include <cuda_runtime.h>
#include <math.h>
#include <stdint.h>

// ---------------- constants ----------------
#define TKN 512
#define DIM 512
#define CCH 256
#define HGT 128
#define WID 128
#define PPT 36
#define PGN 128
#define TOTN 66832
#define CC2 65536

// ---------------- scratch ----------------
__device__ float g_imgT[8 * HGT * WID * CCH];
__device__ float g_hidden[TKN * PGN];
__device__ float g_grid[TKN * PPT * 2];
__device__ float g_params[(size_t)TKN * TOTN];
__device__ float g_sampled[TKN * PPT * CCH];
__device__ float g_h[TKN * PPT * CCH];
__device__ float g_tok[TKN * DIM];
__device__ float g_tok2[TKN * DIM];
__device__ float g_x[TKN * DIM];
__device__ float g_qkv[TKN * 3 * DIM];
__device__ float g_attout[TKN * DIM];
__device__ float g_ff[TKN * 4 * DIM];
__device__ float r_wpg2[PGN * TOTN];
__device__ float r_wout[PPT * CCH * DIM];
__device__ float r_wqkv[DIM * 3 * DIM];
__device__ float r_wproj[DIM * DIM];
__device__ float r_wfc1[DIM * 4 * DIM];
__device__ float r_wfc2[4 * DIM * DIM];

__device__ __forceinline__ float gelu_f(float x) {
    return 0.5f * x * (1.0f + erff(x * 0.70710678118654752440f));
}
__device__ __forceinline__ float f2tf32f(float x) {
    uint32_t r;
    asm("cvt.rna.tf32.f32 %0, %1;" : "=r"(r) : "f"(x));
    return __uint_as_float(r);
}
__device__ __forceinline__ void red2f(float* p, float a, float b) {
    asm volatile("red.global.add.v2.f32 [%0], {%1, %2};"
                 :: "l"(p), "f"(a), "f"(b) : "memory");
}

// ---------------- wpg2 rounding ----------------
#define N4_0 2138624
__global__ void round_pg2_k(const float* __restrict__ w0) {
    int i = blockIdx.x * 256 + threadIdx.x;
    if (i >= N4_0) return;
    float4 v = ((const float4*)w0)[i];
    v.x = f2tf32f(v.x); v.y = f2tf32f(v.y);
    v.z = f2tf32f(v.z); v.w = f2tf32f(v.w);
    ((float4*)r_wpg2)[i] = v;
}

// ---------------- remaining 5 weights ----------------
#define N4_1 1179648
#define N4_2 196608
#define N4_3 65536
#define N4_4 262144
#define N4_5 262144
#define R4_2 (N4_1)
#define R4_3 (R4_2 + N4_2)
#define R4_4 (R4_3 + N4_3)
#define R4_5 (R4_4 + N4_4)
#define R4_T (R4_5 + N4_5)
__global__ void round_rest_k(const float* __restrict__ w1, const float* __restrict__ w2,
                             const float* __restrict__ w3, const float* __restrict__ w4,
                             const float* __restrict__ w5) {
    int i = blockIdx.x * 256 + threadIdx.x;
    if (i >= R4_T) return;
    const float* src; float* dst; int off;
    if      (i < R4_2) { src = w1; dst = r_wout;  off = i; }
    else if (i < R4_3) { src = w2; dst = r_wqkv;  off = i - R4_2; }
    else if (i < R4_4) { src = w3; dst = r_wproj; off = i - R4_3; }
    else if (i < R4_5) { src = w4; dst = r_wfc1;  off = i - R4_4; }
    else               { src = w5; dst = r_wfc2;  off = i - R4_5; }
    float4 v = ((const float4*)src)[off];
    v.x = f2tf32f(v.x); v.y = f2tf32f(v.y);
    v.z = f2tf32f(v.z); v.w = f2tf32f(v.w);
    ((float4*)dst)[off] = v;
}

// ---------------- img transpose ----------------
__global__ void transpose_k(const float* __restrict__ in) {
    __shared__ float tile[32][33];
    int b = blockIdx.z;
    int s0 = blockIdx.x * 32;
    int c0 = blockIdx.y * 32;
    const float* ib = in + (size_t)b * CCH * HGT * WID;
    float* ob = g_imgT + (size_t)b * HGT * WID * CCH;
    int tid = threadIdx.x;
    {
        int c = tid >> 3, s4 = tid & 7;
        float4 v = *(const float4*)(ib + (size_t)(c0 + c) * (HGT * WID) + s0 + 4 * s4);
        tile[4 * s4 + 0][c] = v.x;
        tile[4 * s4 + 1][c] = v.y;
        tile[4 * s4 + 2][c] = v.z;
        tile[4 * s4 + 3][c] = v.w;
    }
    __syncthreads();
    {
        int g = tid & 7, s = tid >> 3;
        float4 v;
        v.x = tile[s][4 * g + 0];
        v.y = tile[s][4 * g + 1];
        v.z = tile[s][4 * g + 2];
        v.w = tile[s][4 * g + 3];
        *(float4*)(ob + (size_t)(s0 + s) * CCH + c0 + 4 * g) = v;
    }
}

// ---------------- per-token pre ----------------
__global__ void pre_k(const float* __restrict__ x, const float* __restrict__ roi,
                      const float* __restrict__ g_off, const float* __restrict__ b_off,
                      const float* __restrict__ w_off, const float* __restrict__ off_bias,
                      const float* __restrict__ g_pg, const float* __restrict__ b_pg,
                      const float* __restrict__ w_pg1, const float* __restrict__ b_pg1) {
    int t = blockIdx.x;
    int tid = threadIdx.x;
    __shared__ float xoff[DIM], xpg[DIM], offs[72];
    __shared__ float rs[4], rs2[4], stats[4];

    const float* xr = x + (size_t)t * DIM;
    float v[4], s = 0.f, s2 = 0.f;
#pragma unroll
    for (int i = 0; i < 4; i++) { v[i] = xr[tid + 128 * i]; s += v[i]; s2 += v[i] * v[i]; }
#pragma unroll
    for (int o = 16; o; o >>= 1) {
        s  += __shfl_down_sync(0xffffffffu, s,  o);
        s2 += __shfl_down_sync(0xffffffffu, s2, o);
    }
    if ((tid & 31) == 0) { rs[tid >> 5] = s; rs2[tid >> 5] = s2; }
    __syncthreads();
    float ts = rs[0] + rs[1] + rs[2] + rs[3];
    float ts2 = rs2[0] + rs2[1] + rs2[2] + rs2[3];
    float mean = ts * (1.f / DIM);
    float var = ts2 * (1.f / DIM) - mean * mean;
    float rstd = rsqrtf(var + 1e-5f);
#pragma unroll
    for (int i = 0; i < 4; i++) {
        int k = tid + 128 * i;
        float xn = (v[i] - mean) * rstd;
        xoff[k] = xn * g_off[k] + b_off[k];
        xpg[k]  = xn * g_pg[k]  + b_pg[k];
    }
    __syncthreads();

    {
        float h = b_pg1[tid];
        for (int k = 0; k < DIM; k++) h = fmaf(xpg[k], w_pg1[k * PGN + tid], h);
        g_hidden[t * PGN + tid] = f2tf32f(h);
    }
    if (tid < 72) {
        float o = off_bias[tid];
        for (int k = 0; k < DIM; k++) o = fmaf(xoff[k], w_off[k * 72 + tid], o);
        offs[tid] = o;
    }
    __syncthreads();
    if (tid < 2) {
        float mu = 0.f;
        for (int p = 0; p < PPT; p++) mu += offs[p * 2 + tid];
        mu *= (1.f / PPT);
        float vv = 0.f;
        for (int p = 0; p < PPT; p++) { float d = offs[p * 2 + tid] - mu; vv += d * d; }
        vv *= (1.f / (PPT - 1));
        stats[tid * 2] = mu;
        stats[tid * 2 + 1] = sqrtf(vv) + 1e-5f;
    }
    __syncthreads();
    if (tid < 72) {
        int coord = tid & 1, p = tid >> 1;
        float mu = stats[coord * 2], sd = stats[coord * 2 + 1];
        float on = (offs[tid] - mu) / (3.f * sd);
        float tl = roi[t * 4 + coord], br = roi[t * 4 + 2 + coord];
        float xy = 0.5f * (tl + br), wh = br - tl;
        float pt = xy + on * wh;
        g_grid[(t * PPT + p) * 2 + coord] = pt * 2.f - 1.f;
    }
}

// ---------------- bilinear grid sample ----------------
__global__ void sample_k() {
    int p = blockIdx.x, t = blockIdx.y;
    int c4 = threadIdx.x << 2;
    int b = t >> 6;
    float gx = g_grid[(t * PPT + p) * 2 + 0];
    float gy = g_grid[(t * PPT + p) * 2 + 1];
    float x = ((gx + 1.f) * WID - 1.f) * 0.5f;
    float y = ((gy + 1.f) * HGT - 1.f) * 0.5f;
    float x0f = floorf(x), y0f = floorf(y);
    float wx = x - x0f, wy = y - y0f;
    int x0 = min(max((int)x0f, 0), WID - 1);
    int x1 = min(max((int)x0f + 1, 0), WID - 1);
    int y0 = min(max((int)y0f, 0), HGT - 1);
    int y1 = min(max((int)y0f + 1, 0), HGT - 1);
    const float* ib = g_imgT + (size_t)b * HGT * WID * CCH;
    float4 v00 = *(const float4*)(ib + (size_t)(y0 * WID + x0) * CCH + c4);
    float4 v01 = *(const float4*)(ib + (size_t)(y0 * WID + x1) * CCH + c4);
    float4 v10 = *(const float4*)(ib + (size_t)(y1 * WID + x0) * CCH + c4);
    float4 v11 = *(const float4*)(ib + (size_t)(y1 * WID + x1) * CCH + c4);
    float w00 = (1.f - wx) * (1.f - wy), w01 = wx * (1.f - wy);
    float w10 = (1.f - wx) * wy,         w11 = wx * wy;
    float4 o;
    o.x = v00.x * w00 + v01.x * w01 + v10.x * w10 + v11.x * w11;
    o.y = v00.y * w00 + v01.y * w01 + v10.y * w10 + v11.y * w11;
    o.z = v00.z * w00 + v01.z * w01 + v10.z * w10 + v11.z * w11;
    o.w = v00.w * w00 + v01.w * w01 + v10.w * w10 + v11.w * w11;
    *(float4*)(g_sampled + ((size_t)t * PPT + p) * CCH + c4) = o;
}

// ---------------- cp.async helpers ----------------
__device__ __forceinline__ void cpa16(uint32_t dst, const void* src, bool pred) {
    int sz = pred ? 16 : 0;
    asm volatile("cp.async.cg.shared.global [%0], [%1], 16, %2;"
                 :: "r"(dst), "l"(src), "r"(sz));
}
__device__ __forceinline__ void cpa_commit() {
    asm volatile("cp.async.commit_group;");
}
__device__ __forceinline__ uint32_t smem_u32(const void* p) {
    uint32_t a;
    asm("{ .reg .u64 t; cvta.to.shared.u64 t, %1; cvt.u32.u64 %0, t; }" : "=r"(a) : "l"(p));
    return a;
}

// ---------------- templated tf32 GEMM ----------------
#define ASZ 4608
template <int TN>
__global__ void __launch_bounds__(256)
mma_gemm_t(const float* __restrict__ A, const float* __restrict__ Bm,
           const float* __restrict__ bias, float* __restrict__ C,
           int M, int N, int K, int rnd, int act) {
    constexpr int BN   = TN * 16;
    constexpr int BSTR = BN + 8;
    constexpr int BSZf = 32 * BSTR;
    constexpr int STGf = ASZ + BSZf;
    constexpr int BIT  = BN / 32;
    constexpr int BQ   = BN / 4;

    extern __shared__ float smf[];
    uint32_t sbase = smem_u32(smf);

    int tid = threadIdx.x;
    int warp = tid >> 5, lane = tid & 31;
    int wr = (warp >> 1) * 32;
    int wc = (warp & 1) * (TN * 8);
    int bR = blockIdx.y * 128, bC = blockIdx.x * BN;
    int nz = gridDim.z;
    int Kc = K / nz;
    int kbeg = blockIdx.z * Kc;
    int ntiles = Kc >> 5;

    float acc[2][TN][4];
#pragma unroll
    for (int a = 0; a < 2; a++)
#pragma unroll
        for (int b = 0; b < TN; b++)
#pragma unroll
            for (int c = 0; c < 4; c++) acc[a][b][c] = 0.f;

    int ar[4], ac[4];
#pragma unroll
    for (int i = 0; i < 4; i++) {
        int f = tid + (i << 8);
        ar[i] = f >> 3;  ac[i] = (f & 7) << 2;
    }
    int br_[BIT], bc_[BIT];
#pragma unroll
    for (int i = 0; i < BIT; i++) {
        int f = tid + (i << 8);
        br_[i] = f / BQ; bc_[i] = (f % BQ) << 2;
    }

    auto issue = [&](int t, int stage) {
        int k0 = kbeg + (t << 5);
        uint32_t sa = sbase + stage * (STGf * 4);
#pragma unroll
        for (int i = 0; i < 4; i++) {
            cpa16(sa + (ar[i] * 36 + ac[i]) * 4,
                  A + (size_t)(bR + ar[i]) * K + k0 + ac[i], true);
        }
        uint32_t sb = sa + ASZ * 4;
#pragma unroll
        for (int i = 0; i < BIT; i++) {
            int gc = bC + bc_[i];
            cpa16(sb + (br_[i] * BSTR + bc_[i]) * 4,
                  Bm + (size_t)(k0 + br_[i]) * N + gc, gc < N);
        }
        cpa_commit();
    };

    issue(0, 0);
    for (int t = 0; t < ntiles; t++) {
        if (t + 1 < ntiles) {
            issue(t + 1, (t + 1) & 1);
            asm volatile("cp.async.wait_group 1;");
        } else {
            asm volatile("cp.async.wait_group 0;");
        }
        __syncthreads();
        const uint32_t* As = (const uint32_t*)(smf + (t & 1) * STGf);
        const uint32_t* Bs = As + ASZ;
#pragma unroll
        for (int k8 = 0; k8 < 4; k8++) {
            int kk = k8 << 3;
            uint32_t afr[2][4];
#pragma unroll
            for (int tm = 0; tm < 2; tm++) {
                int r = wr + tm * 16 + (lane >> 2);
                int c = kk + (lane & 3);
                afr[tm][0] = As[r * 36 + c];
                afr[tm][1] = As[(r + 8) * 36 + c];
                afr[tm][2] = As[r * 36 + c + 4];
                afr[tm][3] = As[(r + 8) * 36 + c + 4];
            }
#pragma unroll
            for (int tn = 0; tn < TN; tn++) {
                int col = wc + tn * 8 + (lane >> 2);
                uint32_t b0 = Bs[(kk + (lane & 3)) * BSTR + col];
                uint32_t b1 = Bs[(kk + (lane & 3) + 4) * BSTR + col];
#pragma unroll
                for (int tm = 0; tm < 2; tm++) {
                    asm volatile(
                        "mma.sync.aligned.m16n8k8.row.col.f32.tf32.tf32.f32 "
                        "{%0,%1,%2,%3}, {%4,%5,%6,%7}, {%8,%9}, {%0,%1,%2,%3};"
                        : "+f"(acc[tm][tn][0]), "+f"(acc[tm][tn][1]),
                          "+f"(acc[tm][tn][2]), "+f"(acc[tm][tn][3])
                        : "r"(afr[tm][0]), "r"(afr[tm][1]),
                          "r"(afr[tm][2]), "r"(afr[tm][3]),
                          "r"(b0), "r"(b1));
                }
            }
        }
        __syncthreads();
    }

    if (nz == 1) {
#pragma unroll
        for (int tm = 0; tm < 2; tm++) {
            int row = bR + wr + tm * 16 + (lane >> 2);
#pragma unroll
            for (int tn = 0; tn < TN; tn++) {
                int col = bC + wc + tn * 8 + ((lane & 3) << 1);
                float bv0 = 0.f, bv1 = 0.f;
                if (bias) {
                    if (col < N) bv0 = bias[col];
                    if (col + 1 < N) bv1 = bias[col + 1];
                }
                float o0 = acc[tm][tn][0] + bv0, o1 = acc[tm][tn][1] + bv1;
                float o2 = acc[tm][tn][2] + bv0, o3 = acc[tm][tn][3] + bv1;
                if (act) {
                    o0 = gelu_f(o0); o1 = gelu_f(o1);
                    o2 = gelu_f(o2); o3 = gelu_f(o3);
                }
                if (rnd | act) {
                    o0 = f2tf32f(o0); o1 = f2tf32f(o1);
                    o2 = f2tf32f(o2); o3 = f2tf32f(o3);
                }
                if (col < N) {
                    C[(size_t)row * N + col] = o0;
                    C[(size_t)(row + 8) * N + col] = o2;
                }
                if (col + 1 < N) {
                    C[(size_t)row * N + col + 1] = o1;
                    C[(size_t)(row + 8) * N + col + 1] = o3;
                }
            }
        }
    } else {
#pragma unroll
        for (int tm = 0; tm < 2; tm++) {
            int row = bR + wr + tm * 16 + (lane >> 2);
#pragma unroll
            for (int tn = 0; tn < TN; tn++) {
                int col = bC + wc + tn * 8 + ((lane & 3) << 1);
                red2f(&C[(size_t)row * N + col], acc[tm][tn][0], acc[tm][tn][1]);
                red2f(&C[(size_t)(row + 8) * N + col], acc[tm][tn][2], acc[tm][tn][3]);
            }
        }
    }
}

// ---------------- init ----------------
__global__ void init_k(const float* __restrict__ resid, const float* __restrict__ bias,
                       float* __restrict__ C, int n, int N) {
    int i = blockIdx.x * 256 + threadIdx.x;
    if (i < n) {
        int col = i % N;
        C[i] = (resid ? resid[i] : 0.f) + bias[col];
    }
}

// ---------------- tensor-core per-token mixing ----------------
#define MIX_ASTR 260
#define MIX_BSTR 264
#define MIX_AF (48 * MIX_ASTR)
#define MIX_BF (32 * MIX_BSTR)
#define MIX_SMF (MIX_AF + 2 * MIX_BF + 1296)
__global__ void __launch_bounds__(256)
mixmma_k(const float* __restrict__ mb, const float* __restrict__ sb) {
    extern __shared__ float smf[];
    float* Aa  = smf;
    float* Bb  = smf + MIX_AF;
    float* sms = smf + MIX_AF + 2 * MIX_BF;
    uint32_t sbase = smem_u32(smf);

    int t = blockIdx.x, tid = threadIdx.x;
    int warp = tid >> 5, lane = tid & 31;
    const float* pt = g_params + (size_t)t * TOTN;

    for (int i = tid; i < 12 * MIX_ASTR; i += 256) Aa[36 * MIX_ASTR + i] = 0.f;
    const float4* sp4 = (const float4*)(g_sampled + (size_t)t * (PPT * CCH));
    for (int i = tid; i < PPT * CCH / 4; i += 256) {
        float4 v = sp4[i];
        int r = i >> 6, c = (i & 63) << 2;
        float* d = Aa + r * MIX_ASTR + c;
        d[0] = f2tf32f(v.x); d[1] = f2tf32f(v.y);
        d[2] = f2tf32f(v.z); d[3] = f2tf32f(v.w);
    }
    for (int i = tid; i < PPT * PPT; i += 256) sms[i] = pt[CC2 + i];

    uint32_t bB = sbase + MIX_AF * 4;
    auto issue = [&](int ch, int stg) {
        const float* src = pt + ch * 32 * 256;
        uint32_t dst = bB + stg * (MIX_BF * 4);
#pragma unroll
        for (int i = 0; i < 8; i++) {
            int e = tid + (i << 8);
            int r = e >> 6, c4 = (e & 63) << 2;
            cpa16(dst + (r * MIX_BSTR + c4) * 4, src + r * 256 + c4, true);
        }
        cpa_commit();
    };

    float acc[3][4][4];
#pragma unroll
    for (int a = 0; a < 3; a++)
#pragma unroll
        for (int b = 0; b < 4; b++)
#pragma unroll
            for (int c = 0; c < 4; c++) acc[a][b][c] = 0.f;

    issue(0, 0);
    for (int ch = 0; ch < 8; ch++) {
        if (ch + 1 < 8) {
            issue(ch + 1, (ch + 1) & 1);
            asm volatile("cp.async.wait_group 1;");
        } else {
            asm volatile("cp.async.wait_group 0;");
        }
        __syncthreads();
        const uint32_t* As = (const uint32_t*)Aa;
        const uint32_t* Bs = (const uint32_t*)(Bb + (ch & 1) * MIX_BF);
#pragma unroll
        for (int k8 = 0; k8 < 4; k8++) {
            int kk = (ch << 5) + (k8 << 3);
            int kb = k8 << 3;
            uint32_t afr[3][4];
#pragma unroll
            for (int mt = 0; mt < 3; mt++) {
                int r = mt * 16 + (lane >> 2);
                int c = kk + (lane & 3);
                afr[mt][0] = As[r * MIX_ASTR + c];
                afr[mt][1] = As[(r + 8) * MIX_ASTR + c];
                afr[mt][2] = As[r * MIX_ASTR + c + 4];
                afr[mt][3] = As[(r + 8) * MIX_ASTR + c + 4];
            }
#pragma unroll
            for (int tn = 0; tn < 4; tn++) {
                int col = warp * 32 + tn * 8 + (lane >> 2);
                uint32_t b0 = Bs[(kb + (lane & 3)) * MIX_BSTR + col];
                uint32_t b1 = Bs[(kb + (lane & 3) + 4) * MIX_BSTR + col];
#pragma unroll
                for (int mt = 0; mt < 3; mt++) {
                    asm volatile(
                        "mma.sync.aligned.m16n8k8.row.col.f32.tf32.tf32.f32 "
                        "{%0,%1,%2,%3}, {%4,%5,%6,%7}, {%8,%9}, {%0,%1,%2,%3};"
                        : "+f"(acc[mt][tn][0]), "+f"(acc[mt][tn][1]),
                          "+f"(acc[mt][tn][2]), "+f"(acc[mt][tn][3])
                        : "r"(afr[mt][0]), "r"(afr[mt][1]),
                          "r"(afr[mt][2]), "r"(afr[mt][3]),
                          "r"(b0), "r"(b1));
                }
            }
        }
        __syncthreads();
    }

    float* hsh = Bb;
#pragma unroll
    for (int mt = 0; mt < 3; mt++) {
#pragma unroll
        for (int half = 0; half < 2; half++) {
            int row = mt * 16 + (lane >> 2) + half * 8;
            if (row >= PPT) continue;
#pragma unroll
            for (int tn = 0; tn < 4; tn++) {
                int col = warp * 32 + tn * 8 + ((lane & 3) << 1);
                hsh[row * 260 + col]     = gelu_f(acc[mt][tn][half * 2 + 0] + mb[col]);
                hsh[row * 260 + col + 1] = gelu_f(acc[mt][tn][half * 2 + 1] + mb[col + 1]);
            }
        }
    }
    __syncthreads();

    int d4 = tid & 63;
    int q0 = (tid >> 6) * 9;
    float4 accq[9];
#pragma unroll
    for (int q = 0; q < 9; q++) {
        float s = sb[q0 + q];
        accq[q] = make_float4(s, s, s, s);
    }
    for (int p = 0; p < PPT; p++) {
        float4 hv = *(const float4*)(hsh + p * 260 + 4 * d4);
#pragma unroll
        for (int q = 0; q < 9; q++) {
            float smv = sms[(q0 + q) * PPT + p];
            accq[q].x = fmaf(smv, hv.x, accq[q].x);
            accq[q].y = fmaf(smv, hv.y, accq[q].y);
            accq[q].z = fmaf(smv, hv.z, accq[q].z);
            accq[q].w = fmaf(smv, hv.w, accq[q].w);
        }
    }
    float* ho = g_h + (size_t)t * (PPT * CCH);
#pragma unroll
    for (int q = 0; q < 9; q++) {
        float4 o;
        o.x = f2tf32f(gelu_f(accq[q].x));
        o.y = f2tf32f(gelu_f(accq[q].y));
        o.z = f2tf32f(gelu_f(accq[q].z));
        o.w = f2tf32f(gelu_f(accq[q].w));
        *(float4*)(ho + (q0 + q) * CCH + 4 * d4) = o;
    }
}

// ---------------- layernorm ----------------
__global__ void ln_k(const float* __restrict__ x, const float* __restrict__ g,
                     const float* __restrict__ bb, float* __restrict__ y) {
    int t = blockIdx.x, tid = threadIdx.x;
    __shared__ float rs[4], rs2[4];
    const float* xr = x + (size_t)t * DIM;
    float v[4], s = 0.f, s2 = 0.f;
#pragma unroll
    for (int i = 0; i < 4; i++) { v[i] = xr[tid + 128 * i]; s += v[i]; s2 += v[i] * v[i]; }
#pragma unroll
    for (int o = 16; o; o >>= 1) {
        s  += __shfl_down_sync(0xffffffffu, s,  o);
        s2 += __shfl_down_sync(0xffffffffu, s2, o);
    }
    if ((tid & 31) == 0) { rs[tid >> 5] = s; rs2[tid >> 5] = s2; }
    __syncthreads();
    float ts = rs[0] + rs[1] + rs[2] + rs[3];
    float ts2 = rs2[0] + rs2[1] + rs2[2] + rs2[3];
    float mean = ts * (1.f / DIM);
    float var = ts2 * (1.f / DIM) - mean * mean;
    float rstd = rsqrtf(var + 1e-5f);
#pragma unroll
    for (int i = 0; i < 4; i++) {
        int k = tid + 128 * i;
        y[(size_t)t * DIM + k] = f2tf32f((v[i] - mean) * rstd * g[k] + bb[k]);
    }
}

// ---------------- attention v2: 128 threads, d-split with smem combine ----------------
// dyn smem: Ks[4096] | Vs[4096] | scp[2][64][64]  -> 16KB+16KB+32KB = 64KB
__global__ void __launch_bounds__(128) attn_k() {
    extern __shared__ float asm_[];
    float* Ks  = asm_;
    float* Vs  = asm_ + 4096;
    float* scp = asm_ + 8192;          // [half][q][k] = half*4096 + q*64 + k

    int b = blockIdx.x, h = blockIdx.y;
    int tid = threadIdx.x;
    int q = tid & 63, half = tid >> 6;
    const float* base = g_qkv + (size_t)b * 64 * (3 * DIM);
    for (int i = tid; i < 64 * 64; i += 128) {
        int n = i >> 6, d2 = i & 63;
        Ks[i] = base[(size_t)n * (3 * DIM) + DIM     + h * 64 + d2];
        Vs[i] = base[(size_t)n * (3 * DIM) + 2 * DIM + h * 64 + d2];
    }
    float qreg[32];
    const float* qrow = base + (size_t)q * (3 * DIM) + h * 64 + half * 32;
#pragma unroll
    for (int j = 0; j < 32; j++) qreg[j] = qrow[j];
    __syncthreads();

    // partial scores over this thread's 32-d slice
#pragma unroll 4
    for (int k = 0; k < 64; k++) {
        float s = 0.f;
#pragma unroll
        for (int j = 0; j < 32; j++) s = fmaf(qreg[j], Ks[k * 64 + half * 32 + j], s);
        scp[half * 4096 + q * 64 + k] = s;
    }
    __syncthreads();

    // softmax on half 0 threads
    if (half == 0) {
        float sc[64];
        float mx = -1e30f;
#pragma unroll
        for (int k = 0; k < 64; k++) {
            sc[k] = (scp[q * 64 + k] + scp[4096 + q * 64 + k]) * 0.125f;
            mx = fmaxf(mx, sc[k]);
        }
        float sum = 0.f;
#pragma unroll
        for (int k = 0; k < 64; k++) { sc[k] = expf(sc[k] - mx); sum += sc[k]; }
        float inv = 1.f / sum;
#pragma unroll
        for (int k = 0; k < 64; k++) scp[q * 64 + k] = sc[k] * inv;
    }
    __syncthreads();

    // output: this thread's 32-d slice
    float* orow = g_attout + (size_t)(b * 64 + q) * DIM + h * 64 + half * 32;
#pragma unroll 4
    for (int d2 = 0; d2 < 32; d2++) {
        float o = 0.f;
#pragma unroll
        for (int k = 0; k < 64; k++) o = fmaf(scp[q * 64 + k], Vs[k * 64 + half * 32 + d2], o);
        orow[d2] = f2tf32f(o);
    }
}

// ---------------- streams / events ----------------
#define DSM8 (2 * (ASZ + 32 * 136) * 4)
#define DSM4 (2 * (ASZ + 32 * 72) * 4)
#define DSMA ((4096 + 4096 + 8192) * 4)
struct SfStreams {
    cudaStream_t s1, s2;
    cudaEvent_t e_root, e_pre, e_rpg2, e_inits, e_sample, e_wout, e_t2, e_proj, e_outi;
    SfStreams() {
        cudaStreamCreateWithFlags(&s1, cudaStreamNonBlocking);
        cudaStreamCreateWithFlags(&s2, cudaStreamNonBlocking);
        cudaEventCreateWithFlags(&e_root,   cudaEventDisableTiming);
        cudaEventCreateWithFlags(&e_pre,    cudaEventDisableTiming);
        cudaEventCreateWithFlags(&e_rpg2,   cudaEventDisableTiming);
        cudaEventCreateWithFlags(&e_inits,  cudaEventDisableTiming);
        cudaEventCreateWithFlags(&e_sample, cudaEventDisableTiming);
        cudaEventCreateWithFlags(&e_wout,   cudaEventDisableTiming);
        cudaEventCreateWithFlags(&e_t2,     cudaEventDisableTiming);
        cudaEventCreateWithFlags(&e_proj,   cudaEventDisableTiming);
        cudaEventCreateWithFlags(&e_outi,   cudaEventDisableTiming);
        cudaFuncSetAttribute(mma_gemm_t<8>, cudaFuncAttributeMaxDynamicSharedMemorySize, DSM8);
        cudaFuncSetAttribute(mma_gemm_t<4>, cudaFuncAttributeMaxDynamicSharedMemorySize, DSM4);
        cudaFuncSetAttribute(mixmma_k, cudaFuncAttributeMaxDynamicSharedMemorySize,
                             MIX_SMF * 4);
        cudaFuncSetAttribute(attn_k, cudaFuncAttributeMaxDynamicSharedMemorySize, DSMA);
    }
};
static SfStreams g_sf;

// ---------------- launch ----------------
extern "C" void kernel_launch(void* const* d_in, const int* in_sizes, int n_in,
                              void* d_out, int out_size) {
    const float* token_embed = (const float*)d_in[0];
    const float* token_roi   = (const float*)d_in[1];
    const float* img_feat    = (const float*)d_in[2];
    const float* ln_off_g    = (const float*)d_in[3];
    const float* ln_off_b    = (const float*)d_in[4];
    const float* w_off       = (const float*)d_in[5];
    const float* off_bias    = (const float*)d_in[6];
    const float* ln_pg_g     = (const float*)d_in[7];
    const float* ln_pg_b     = (const float*)d_in[8];
    const float* w_pg1       = (const float*)d_in[9];
    const float* b_pg1       = (const float*)d_in[10];
    const float* w_pg2       = (const float*)d_in[11];
    const float* b_pg2       = (const float*)d_in[12];
    const float* m_beta      = (const float*)d_in[13];
    const float* s_beta      = (const float*)d_in[14];
    const float* w_out       = (const float*)d_in[15];
    const float* b_out       = (const float*)d_in[16];
    const float* ln1_g       = (const float*)d_in[17];
    const float* ln1_b       = (const float*)d_in[18];
    const float* w_qkv       = (const float*)d_in[19];
    const float* b_qkv       = (const float*)d_in[20];
    const float* w_proj      = (const float*)d_in[21];
    const float* b_proj      = (const float*)d_in[22];
    const float* ln2_g       = (const float*)d_in[23];
    const float* ln2_b       = (const float*)d_in[24];
    const float* w_fc1       = (const float*)d_in[25];
    const float* b_fc1       = (const float*)d_in[26];
    const float* w_fc2       = (const float*)d_in[27];
    const float* b_fc2       = (const float*)d_in[28];
    float* out = (float*)d_out;

    void* p;
    cudaGetSymbolAddress(&p, g_hidden);  float* hidden = (float*)p;
    cudaGetSymbolAddress(&p, g_params);  float* params = (float*)p;
    cudaGetSymbolAddress(&p, g_h);       float* hbuf   = (float*)p;
    cudaGetSymbolAddress(&p, g_tok);     float* tok    = (float*)p;
    cudaGetSymbolAddress(&p, g_tok2);    float* tok2   = (float*)p;
    cudaGetSymbolAddress(&p, g_x);       float* xbuf   = (float*)p;
    cudaGetSymbolAddress(&p, g_qkv);     float* qkv    = (float*)p;
    cudaGetSymbolAddress(&p, g_attout);  float* attout = (float*)p;
    cudaGetSymbolAddress(&p, g_ff);      float* ff     = (float*)p;
    cudaGetSymbolAddress(&p, r_wpg2);    float* rwpg2  = (float*)p;
    cudaGetSymbolAddress(&p, r_wout);    float* rwout  = (float*)p;
    cudaGetSymbolAddress(&p, r_wqkv);    float* rwqkv  = (float*)p;
    cudaGetSymbolAddress(&p, r_wproj);   float* rwproj = (float*)p;
    cudaGetSymbolAddress(&p, r_wfc1);    float* rwfc1  = (float*)p;
    cudaGetSymbolAddress(&p, r_wfc2);    float* rwfc2  = (float*)p;

    const int DSMX = MIX_SMF * 4;
    cudaStream_t s0 = 0, s1 = g_sf.s1, s2 = g_sf.s2;

    // ---- fork ----
    cudaEventRecord(g_sf.e_root, s0);
    cudaStreamWaitEvent(s1, g_sf.e_root, 0);
    cudaStreamWaitEvent(s2, g_sf.e_root, 0);

    // Issue order tuned so profiler window (skip 5) lands on heavy kernels:
    // 1 pre, 2 round_pg2, 3 round_rest, 4 params, 5 transpose, 6 sample, 7 mix...
    // s0: pre_k
    pre_k<<<TKN, 128, 0, s0>>>(token_embed, token_roi, ln_off_g, ln_off_b, w_off, off_bias,
                               ln_pg_g, ln_pg_b, w_pg1, b_pg1);
    cudaEventRecord(g_sf.e_pre, s0);

    // s1: wpg2 rounding, then rest
    round_pg2_k<<<(N4_0 + 255) / 256, 256, 0, s1>>>(w_pg2);
    cudaEventRecord(g_sf.e_rpg2, s1);
    round_rest_k<<<(R4_T + 255) / 256, 256, 0, s1>>>(w_out, w_qkv, w_proj, w_fc1, w_fc2);

    // s0: params GEMM (TN=8) — launch #4
    cudaStreamWaitEvent(s0, g_sf.e_rpg2, 0);
    mma_gemm_t<8><<<dim3((TOTN + 127) / 128, TKN / 128, 1), 256, DSM8, s0>>>(
        hidden, rwpg2, b_pg2, params, TKN, TOTN, PGN, 1, 0);

    // s2: transpose (#5), then sampling (#6)
    transpose_k<<<dim3((HGT * WID) / 32, CCH / 32, 8), 256, 0, s2>>>(img_feat);
    cudaStreamWaitEvent(s2, g_sf.e_pre, 0);
    sample_k<<<dim3(PPT, TKN), 64, 0, s2>>>();
    cudaEventRecord(g_sf.e_sample, s2);

    // s0: mixing (#7)
    cudaStreamWaitEvent(s0, g_sf.e_sample, 0);
    mixmma_k<<<TKN, 256, DSMX, s0>>>(m_beta, s_beta);

    // s1: inits (after rounding; off critical path)
    init_k<<<(TKN * DIM + 255) / 256, 256, 0, s1>>>(token_embed, b_out, tok, TKN * DIM, DIM);
    init_k<<<(TKN * 3 * DIM + 255) / 256, 256, 0, s1>>>(nullptr, b_qkv, qkv, TKN * 3 * DIM, 3 * DIM);
    cudaEventRecord(g_sf.e_inits, s1);

    // s0: w_out GEMM (TN=4, splitK16)
    cudaStreamWaitEvent(s0, g_sf.e_inits, 0);
    mma_gemm_t<4><<<dim3(DIM / 64, TKN / 128, 16), 256, DSM4, s0>>>(
        hbuf, rwout, nullptr, tok, TKN, DIM, PPT * CCH, 0, 0);
    cudaEventRecord(g_sf.e_wout, s0);

    // s1: init_tok2 in parallel
    cudaStreamWaitEvent(s1, g_sf.e_wout, 0);
    init_k<<<(TKN * DIM + 255) / 256, 256, 0, s1>>>(tok, b_proj, tok2, TKN * DIM, DIM);
    cudaEventRecord(g_sf.e_t2, s1);

    // s0: LN1 -> qkv -> attention
    ln_k<<<TKN, 128, 0, s0>>>(tok, ln1_g, ln1_b, xbuf);
    mma_gemm_t<4><<<dim3((3 * DIM) / 64, TKN / 128, 4), 256, DSM4, s0>>>(
        xbuf, rwqkv, nullptr, qkv, TKN, 3 * DIM, DIM, 0, 0);
    attn_k<<<dim3(8, 8), 128, DSMA, s0>>>();
    // s0: proj
    cudaStreamWaitEvent(s0, g_sf.e_t2, 0);
    mma_gemm_t<4><<<dim3(DIM / 64, TKN / 128, 8), 256, DSM4, s0>>>(
        attout, rwproj, nullptr, tok2, TKN, DIM, DIM, 0, 0);
    cudaEventRecord(g_sf.e_proj, s0);

    // s2: init_out in parallel
    cudaStreamWaitEvent(s2, g_sf.e_proj, 0);
    init_k<<<(TKN * DIM + 255) / 256, 256, 0, s2>>>(tok2, b_fc2, out, TKN * DIM, DIM);
    cudaEventRecord(g_sf.e_outi, s2);

    // s0: LN2 -> fc1 (fused bias+gelu) -> fc2
    ln_k<<<TKN, 128, 0, s0>>>(tok2, ln2_g, ln2_b, xbuf);
    mma_gemm_t<4><<<dim3((4 * DIM) / 64, TKN / 128, 1), 256, DSM4, s0>>>(
        xbuf, rwfc1, b_fc1, ff, TKN, 4 * DIM, DIM, 0, 1);
    cudaStreamWaitEvent(s0, g_sf.e_outi, 0);
    mma_gemm_t<4><<<dim3(DIM / 64, TKN / 128, 16), 256, DSM4, s0>>>(
        ff, rwfc2, nullptr, out, TKN, DIM, 4 * DIM, 0, 0);
}

// round 12
// speedup vs baseline: 1.0707x; 1.0073x over previous
#include <cuda_runtime.h>
#include <math.h>
#include <stdint.h>

// ---------------- constants ----------------
#define TKN 512
#define DIM 512
#define CCH 256
#define HGT 128
#define WID 128
#define PPT 36
#define PGN 128
#define TOTN 66832
#define CC2 65536

// ---------------- scratch ----------------
__device__ float g_imgT[8 * HGT * WID * CCH];
__device__ float g_hidden[TKN * PGN];
__device__ float g_grid[TKN * PPT * 2];
__device__ float g_params[(size_t)TKN * TOTN];
__device__ float g_sampled[TKN * PPT * CCH];
__device__ float g_h[TKN * PPT * CCH];
__device__ float g_tok[TKN * DIM];
__device__ float g_tok2[TKN * DIM];
__device__ float g_x[TKN * DIM];
__device__ float g_qkv[TKN * 3 * DIM];
__device__ float g_attout[TKN * DIM];
__device__ float g_ff[TKN * 4 * DIM];
__device__ float r_wpg2[PGN * TOTN];
__device__ float r_wout[PPT * CCH * DIM];
__device__ float r_wqkv[DIM * 3 * DIM];
__device__ float r_wproj[DIM * DIM];
__device__ float r_wfc1[DIM * 4 * DIM];
__device__ float r_wfc2[4 * DIM * DIM];

__device__ __forceinline__ float gelu_f(float x) {
    return 0.5f * x * (1.0f + erff(x * 0.70710678118654752440f));
}
__device__ __forceinline__ float f2tf32f(float x) {
    uint32_t r;
    asm("cvt.rna.tf32.f32 %0, %1;" : "=r"(r) : "f"(x));
    return __uint_as_float(r);
}
__device__ __forceinline__ void red2f(float* p, float a, float b) {
    asm volatile("red.global.add.v2.f32 [%0], {%1, %2};"
                 :: "l"(p), "f"(a), "f"(b) : "memory");
}

// ---------------- wpg2 rounding ----------------
#define N4_0 2138624
__global__ void round_pg2_k(const float* __restrict__ w0) {
    int i = blockIdx.x * 256 + threadIdx.x;
    if (i >= N4_0) return;
    float4 v = ((const float4*)w0)[i];
    v.x = f2tf32f(v.x); v.y = f2tf32f(v.y);
    v.z = f2tf32f(v.z); v.w = f2tf32f(v.w);
    ((float4*)r_wpg2)[i] = v;
}

// ---------------- remaining 5 weights ----------------
#define N4_1 1179648
#define N4_2 196608
#define N4_3 65536
#define N4_4 262144
#define N4_5 262144
#define R4_2 (N4_1)
#define R4_3 (R4_2 + N4_2)
#define R4_4 (R4_3 + N4_3)
#define R4_5 (R4_4 + N4_4)
#define R4_T (R4_5 + N4_5)
__global__ void round_rest_k(const float* __restrict__ w1, const float* __restrict__ w2,
                             const float* __restrict__ w3, const float* __restrict__ w4,
                             const float* __restrict__ w5) {
    int i = blockIdx.x * 256 + threadIdx.x;
    if (i >= R4_T) return;
    const float* src; float* dst; int off;
    if      (i < R4_2) { src = w1; dst = r_wout;  off = i; }
    else if (i < R4_3) { src = w2; dst = r_wqkv;  off = i - R4_2; }
    else if (i < R4_4) { src = w3; dst = r_wproj; off = i - R4_3; }
    else if (i < R4_5) { src = w4; dst = r_wfc1;  off = i - R4_4; }
    else               { src = w5; dst = r_wfc2;  off = i - R4_5; }
    float4 v = ((const float4*)src)[off];
    v.x = f2tf32f(v.x); v.y = f2tf32f(v.y);
    v.z = f2tf32f(v.z); v.w = f2tf32f(v.w);
    ((float4*)dst)[off] = v;
}

// ---------------- img transpose ----------------
__global__ void transpose_k(const float* __restrict__ in) {
    __shared__ float tile[32][33];
    int b = blockIdx.z;
    int s0 = blockIdx.x * 32;
    int c0 = blockIdx.y * 32;
    const float* ib = in + (size_t)b * CCH * HGT * WID;
    float* ob = g_imgT + (size_t)b * HGT * WID * CCH;
    int tid = threadIdx.x;
    {
        int c = tid >> 3, s4 = tid & 7;
        float4 v = *(const float4*)(ib + (size_t)(c0 + c) * (HGT * WID) + s0 + 4 * s4);
        tile[4 * s4 + 0][c] = v.x;
        tile[4 * s4 + 1][c] = v.y;
        tile[4 * s4 + 2][c] = v.z;
        tile[4 * s4 + 3][c] = v.w;
    }
    __syncthreads();
    {
        int g = tid & 7, s = tid >> 3;
        float4 v;
        v.x = tile[s][4 * g + 0];
        v.y = tile[s][4 * g + 1];
        v.z = tile[s][4 * g + 2];
        v.w = tile[s][4 * g + 3];
        *(float4*)(ob + (size_t)(s0 + s) * CCH + c0 + 4 * g) = v;
    }
}

// ---------------- per-token pre ----------------
__global__ void pre_k(const float* __restrict__ x, const float* __restrict__ roi,
                      const float* __restrict__ g_off, const float* __restrict__ b_off,
                      const float* __restrict__ w_off, const float* __restrict__ off_bias,
                      const float* __restrict__ g_pg, const float* __restrict__ b_pg,
                      const float* __restrict__ w_pg1, const float* __restrict__ b_pg1) {
    int t = blockIdx.x;
    int tid = threadIdx.x;
    __shared__ float xoff[DIM], xpg[DIM], offs[72];
    __shared__ float rs[4], rs2[4], stats[4];

    const float* xr = x + (size_t)t * DIM;
    float v[4], s = 0.f, s2 = 0.f;
#pragma unroll
    for (int i = 0; i < 4; i++) { v[i] = xr[tid + 128 * i]; s += v[i]; s2 += v[i] * v[i]; }
#pragma unroll
    for (int o = 16; o; o >>= 1) {
        s  += __shfl_down_sync(0xffffffffu, s,  o);
        s2 += __shfl_down_sync(0xffffffffu, s2, o);
    }
    if ((tid & 31) == 0) { rs[tid >> 5] = s; rs2[tid >> 5] = s2; }
    __syncthreads();
    float ts = rs[0] + rs[1] + rs[2] + rs[3];
    float ts2 = rs2[0] + rs2[1] + rs2[2] + rs2[3];
    float mean = ts * (1.f / DIM);
    float var = ts2 * (1.f / DIM) - mean * mean;
    float rstd = rsqrtf(var + 1e-5f);
#pragma unroll
    for (int i = 0; i < 4; i++) {
        int k = tid + 128 * i;
        float xn = (v[i] - mean) * rstd;
        xoff[k] = xn * g_off[k] + b_off[k];
        xpg[k]  = xn * g_pg[k]  + b_pg[k];
    }
    __syncthreads();

    {
        float h = b_pg1[tid];
        for (int k = 0; k < DIM; k++) h = fmaf(xpg[k], w_pg1[k * PGN + tid], h);
        g_hidden[t * PGN + tid] = f2tf32f(h);
    }
    if (tid < 72) {
        float o = off_bias[tid];
        for (int k = 0; k < DIM; k++) o = fmaf(xoff[k], w_off[k * 72 + tid], o);
        offs[tid] = o;
    }
    __syncthreads();
    if (tid < 2) {
        float mu = 0.f;
        for (int p = 0; p < PPT; p++) mu += offs[p * 2 + tid];
        mu *= (1.f / PPT);
        float vv = 0.f;
        for (int p = 0; p < PPT; p++) { float d = offs[p * 2 + tid] - mu; vv += d * d; }
        vv *= (1.f / (PPT - 1));
        stats[tid * 2] = mu;
        stats[tid * 2 + 1] = sqrtf(vv) + 1e-5f;
    }
    __syncthreads();
    if (tid < 72) {
        int coord = tid & 1, p = tid >> 1;
        float mu = stats[coord * 2], sd = stats[coord * 2 + 1];
        float on = (offs[tid] - mu) / (3.f * sd);
        float tl = roi[t * 4 + coord], br = roi[t * 4 + 2 + coord];
        float xy = 0.5f * (tl + br), wh = br - tl;
        float pt = xy + on * wh;
        g_grid[(t * PPT + p) * 2 + coord] = pt * 2.f - 1.f;
    }
}

// ---------------- bilinear grid sample ----------------
__global__ void sample_k() {
    int p = blockIdx.x, t = blockIdx.y;
    int c4 = threadIdx.x << 2;
    int b = t >> 6;
    float gx = g_grid[(t * PPT + p) * 2 + 0];
    float gy = g_grid[(t * PPT + p) * 2 + 1];
    float x = ((gx + 1.f) * WID - 1.f) * 0.5f;
    float y = ((gy + 1.f) * HGT - 1.f) * 0.5f;
    float x0f = floorf(x), y0f = floorf(y);
    float wx = x - x0f, wy = y - y0f;
    int x0 = min(max((int)x0f, 0), WID - 1);
    int x1 = min(max((int)x0f + 1, 0), WID - 1);
    int y0 = min(max((int)y0f, 0), HGT - 1);
    int y1 = min(max((int)y0f + 1, 0), HGT - 1);
    const float* ib = g_imgT + (size_t)b * HGT * WID * CCH;
    float4 v00 = *(const float4*)(ib + (size_t)(y0 * WID + x0) * CCH + c4);
    float4 v01 = *(const float4*)(ib + (size_t)(y0 * WID + x1) * CCH + c4);
    float4 v10 = *(const float4*)(ib + (size_t)(y1 * WID + x0) * CCH + c4);
    float4 v11 = *(const float4*)(ib + (size_t)(y1 * WID + x1) * CCH + c4);
    float w00 = (1.f - wx) * (1.f - wy), w01 = wx * (1.f - wy);
    float w10 = (1.f - wx) * wy,         w11 = wx * wy;
    float4 o;
    o.x = v00.x * w00 + v01.x * w01 + v10.x * w10 + v11.x * w11;
    o.y = v00.y * w00 + v01.y * w01 + v10.y * w10 + v11.y * w11;
    o.z = v00.z * w00 + v01.z * w01 + v10.z * w10 + v11.z * w11;
    o.w = v00.w * w00 + v01.w * w01 + v10.w * w10 + v11.w * w11;
    *(float4*)(g_sampled + ((size_t)t * PPT + p) * CCH + c4) = o;
}

// ---------------- cp.async helpers ----------------
__device__ __forceinline__ void cpa16(uint32_t dst, const void* src, bool pred) {
    int sz = pred ? 16 : 0;
    asm volatile("cp.async.cg.shared.global [%0], [%1], 16, %2;"
                 :: "r"(dst), "l"(src), "r"(sz));
}
__device__ __forceinline__ void cpa_commit() {
    asm volatile("cp.async.commit_group;");
}
__device__ __forceinline__ uint32_t smem_u32(const void* p) {
    uint32_t a;
    asm("{ .reg .u64 t; cvta.to.shared.u64 t, %1; cvt.u32.u64 %0, t; }" : "=r"(a) : "l"(p));
    return a;
}

// ---------------- templated tf32 GEMM: 3-buffer pipeline, 1 barrier/ktile ----------------
#define ASZ 4608
template <int TN>
__global__ void __launch_bounds__(256)
mma_gemm_t(const float* __restrict__ A, const float* __restrict__ Bm,
           const float* __restrict__ bias, float* __restrict__ C,
           int M, int N, int K, int rnd, int act) {
    constexpr int BN   = TN * 16;
    constexpr int BSTR = BN + 8;
    constexpr int BSZf = 32 * BSTR;
    constexpr int STGf = ASZ + BSZf;
    constexpr int BIT  = BN / 32;
    constexpr int BQ   = BN / 4;

    extern __shared__ float smf[];
    uint32_t sbase = smem_u32(smf);

    int tid = threadIdx.x;
    int warp = tid >> 5, lane = tid & 31;
    int wr = (warp >> 1) * 32;
    int wc = (warp & 1) * (TN * 8);
    int bR = blockIdx.y * 128, bC = blockIdx.x * BN;
    int nz = gridDim.z;
    int Kc = K / nz;
    int kbeg = blockIdx.z * Kc;
    int ntiles = Kc >> 5;

    float acc[2][TN][4];
#pragma unroll
    for (int a = 0; a < 2; a++)
#pragma unroll
        for (int b = 0; b < TN; b++)
#pragma unroll
            for (int c = 0; c < 4; c++) acc[a][b][c] = 0.f;

    int ar[4], ac[4];
#pragma unroll
    for (int i = 0; i < 4; i++) {
        int f = tid + (i << 8);
        ar[i] = f >> 3;  ac[i] = (f & 7) << 2;
    }
    int br_[BIT], bc_[BIT];
#pragma unroll
    for (int i = 0; i < BIT; i++) {
        int f = tid + (i << 8);
        br_[i] = f / BQ; bc_[i] = (f % BQ) << 2;
    }

    auto issue = [&](int t, int stage) {
        int k0 = kbeg + (t << 5);
        uint32_t sa = sbase + stage * (STGf * 4);
#pragma unroll
        for (int i = 0; i < 4; i++) {
            cpa16(sa + (ar[i] * 36 + ac[i]) * 4,
                  A + (size_t)(bR + ar[i]) * K + k0 + ac[i], true);
        }
        uint32_t sb = sa + ASZ * 4;
#pragma unroll
        for (int i = 0; i < BIT; i++) {
            int gc = bC + bc_[i];
            cpa16(sb + (br_[i] * BSTR + bc_[i]) * 4,
                  Bm + (size_t)(k0 + br_[i]) * N + gc, gc < N);
        }
        cpa_commit();
    };

    // 3-buffer, depth-2 prefetch, single barrier per ktile
    issue(0, 0);
    if (ntiles > 1) issue(1, 1);
    int rd = 0;            // buffer being read this iteration
    int wrb = 2;           // buffer to write 2-ahead
    for (int t = 0; t < ntiles; t++) {
        if (t + 1 < ntiles) {
            asm volatile("cp.async.wait_group 1;");
        } else {
            asm volatile("cp.async.wait_group 0;");
        }
        __syncthreads();
        if (t + 2 < ntiles) {
            issue(t + 2, wrb);
            wrb = (wrb == 2) ? 0 : wrb + 1;
        }
        const uint32_t* As = (const uint32_t*)(smf + rd * STGf);
        const uint32_t* Bs = As + ASZ;
        rd = (rd == 2) ? 0 : rd + 1;
#pragma unroll
        for (int k8 = 0; k8 < 4; k8++) {
            int kk = k8 << 3;
            uint32_t afr[2][4];
#pragma unroll
            for (int tm = 0; tm < 2; tm++) {
                int r = wr + tm * 16 + (lane >> 2);
                int c = kk + (lane & 3);
                afr[tm][0] = As[r * 36 + c];
                afr[tm][1] = As[(r + 8) * 36 + c];
                afr[tm][2] = As[r * 36 + c + 4];
                afr[tm][3] = As[(r + 8) * 36 + c + 4];
            }
#pragma unroll
            for (int tn = 0; tn < TN; tn++) {
                int col = wc + tn * 8 + (lane >> 2);
                uint32_t b0 = Bs[(kk + (lane & 3)) * BSTR + col];
                uint32_t b1 = Bs[(kk + (lane & 3) + 4) * BSTR + col];
#pragma unroll
                for (int tm = 0; tm < 2; tm++) {
                    asm volatile(
                        "mma.sync.aligned.m16n8k8.row.col.f32.tf32.tf32.f32 "
                        "{%0,%1,%2,%3}, {%4,%5,%6,%7}, {%8,%9}, {%0,%1,%2,%3};"
                        : "+f"(acc[tm][tn][0]), "+f"(acc[tm][tn][1]),
                          "+f"(acc[tm][tn][2]), "+f"(acc[tm][tn][3])
                        : "r"(afr[tm][0]), "r"(afr[tm][1]),
                          "r"(afr[tm][2]), "r"(afr[tm][3]),
                          "r"(b0), "r"(b1));
                }
            }
        }
    }

    if (nz == 1) {
#pragma unroll
        for (int tm = 0; tm < 2; tm++) {
            int row = bR + wr + tm * 16 + (lane >> 2);
#pragma unroll
            for (int tn = 0; tn < TN; tn++) {
                int col = bC + wc + tn * 8 + ((lane & 3) << 1);
                if (col >= N) continue;   // col even, N even -> col+1 < N too
                float bv0 = 0.f, bv1 = 0.f;
                if (bias) { bv0 = bias[col]; bv1 = bias[col + 1]; }
                float o0 = acc[tm][tn][0] + bv0, o1 = acc[tm][tn][1] + bv1;
                float o2 = acc[tm][tn][2] + bv0, o3 = acc[tm][tn][3] + bv1;
                if (act) {
                    o0 = gelu_f(o0); o1 = gelu_f(o1);
                    o2 = gelu_f(o2); o3 = gelu_f(o3);
                }
                if (rnd | act) {
                    o0 = f2tf32f(o0); o1 = f2tf32f(o1);
                    o2 = f2tf32f(o2); o3 = f2tf32f(o3);
                }
                *(float2*)(&C[(size_t)row * N + col])       = make_float2(o0, o1);
                *(float2*)(&C[(size_t)(row + 8) * N + col]) = make_float2(o2, o3);
            }
        }
    } else {
#pragma unroll
        for (int tm = 0; tm < 2; tm++) {
            int row = bR + wr + tm * 16 + (lane >> 2);
#pragma unroll
            for (int tn = 0; tn < TN; tn++) {
                int col = bC + wc + tn * 8 + ((lane & 3) << 1);
                red2f(&C[(size_t)row * N + col], acc[tm][tn][0], acc[tm][tn][1]);
                red2f(&C[(size_t)(row + 8) * N + col], acc[tm][tn][2], acc[tm][tn][3]);
            }
        }
    }
}

// ---------------- init ----------------
__global__ void init_k(const float* __restrict__ resid, const float* __restrict__ bias,
                       float* __restrict__ C, int n, int N) {
    int i = blockIdx.x * 256 + threadIdx.x;
    if (i < n) {
        int col = i % N;
        C[i] = (resid ? resid[i] : 0.f) + bias[col];
    }
}

// ---------------- tensor-core per-token mixing ----------------
#define MIX_ASTR 260
#define MIX_BSTR 264
#define MIX_AF (48 * MIX_ASTR)
#define MIX_BF (32 * MIX_BSTR)
#define MIX_SMF (MIX_AF + 2 * MIX_BF + 1296)
__global__ void __launch_bounds__(256)
mixmma_k(const float* __restrict__ mb, const float* __restrict__ sb) {
    extern __shared__ float smf[];
    float* Aa  = smf;
    float* Bb  = smf + MIX_AF;
    float* sms = smf + MIX_AF + 2 * MIX_BF;
    uint32_t sbase = smem_u32(smf);

    int t = blockIdx.x, tid = threadIdx.x;
    int warp = tid >> 5, lane = tid & 31;
    const float* pt = g_params + (size_t)t * TOTN;

    for (int i = tid; i < 12 * MIX_ASTR; i += 256) Aa[36 * MIX_ASTR + i] = 0.f;
    const float4* sp4 = (const float4*)(g_sampled + (size_t)t * (PPT * CCH));
    for (int i = tid; i < PPT * CCH / 4; i += 256) {
        float4 v = sp4[i];
        int r = i >> 6, c = (i & 63) << 2;
        float* d = Aa + r * MIX_ASTR + c;
        d[0] = f2tf32f(v.x); d[1] = f2tf32f(v.y);
        d[2] = f2tf32f(v.z); d[3] = f2tf32f(v.w);
    }
    for (int i = tid; i < PPT * PPT; i += 256) sms[i] = pt[CC2 + i];

    uint32_t bB = sbase + MIX_AF * 4;
    auto issue = [&](int ch, int stg) {
        const float* src = pt + ch * 32 * 256;
        uint32_t dst = bB + stg * (MIX_BF * 4);
#pragma unroll
        for (int i = 0; i < 8; i++) {
            int e = tid + (i << 8);
            int r = e >> 6, c4 = (e & 63) << 2;
            cpa16(dst + (r * MIX_BSTR + c4) * 4, src + r * 256 + c4, true);
        }
        cpa_commit();
    };

    float acc[3][4][4];
#pragma unroll
    for (int a = 0; a < 3; a++)
#pragma unroll
        for (int b = 0; b < 4; b++)
#pragma unroll
            for (int c = 0; c < 4; c++) acc[a][b][c] = 0.f;

    issue(0, 0);
    for (int ch = 0; ch < 8; ch++) {
        if (ch + 1 < 8) {
            issue(ch + 1, (ch + 1) & 1);
            asm volatile("cp.async.wait_group 1;");
        } else {
            asm volatile("cp.async.wait_group 0;");
        }
        __syncthreads();
        const uint32_t* As = (const uint32_t*)Aa;
        const uint32_t* Bs = (const uint32_t*)(Bb + (ch & 1) * MIX_BF);
#pragma unroll
        for (int k8 = 0; k8 < 4; k8++) {
            int kk = (ch << 5) + (k8 << 3);
            int kb = k8 << 3;
            uint32_t afr[3][4];
#pragma unroll
            for (int mt = 0; mt < 3; mt++) {
                int r = mt * 16 + (lane >> 2);
                int c = kk + (lane & 3);
                afr[mt][0] = As[r * MIX_ASTR + c];
                afr[mt][1] = As[(r + 8) * MIX_ASTR + c];
                afr[mt][2] = As[r * MIX_ASTR + c + 4];
                afr[mt][3] = As[(r + 8) * MIX_ASTR + c + 4];
            }
#pragma unroll
            for (int tn = 0; tn < 4; tn++) {
                int col = warp * 32 + tn * 8 + (lane >> 2);
                uint32_t b0 = Bs[(kb + (lane & 3)) * MIX_BSTR + col];
                uint32_t b1 = Bs[(kb + (lane & 3) + 4) * MIX_BSTR + col];
#pragma unroll
                for (int mt = 0; mt < 3; mt++) {
                    asm volatile(
                        "mma.sync.aligned.m16n8k8.row.col.f32.tf32.tf32.f32 "
                        "{%0,%1,%2,%3}, {%4,%5,%6,%7}, {%8,%9}, {%0,%1,%2,%3};"
                        : "+f"(acc[mt][tn][0]), "+f"(acc[mt][tn][1]),
                          "+f"(acc[mt][tn][2]), "+f"(acc[mt][tn][3])
                        : "r"(afr[mt][0]), "r"(afr[mt][1]),
                          "r"(afr[mt][2]), "r"(afr[mt][3]),
                          "r"(b0), "r"(b1));
                }
            }
        }
        __syncthreads();
    }

    float* hsh = Bb;
#pragma unroll
    for (int mt = 0; mt < 3; mt++) {
#pragma unroll
        for (int half = 0; half < 2; half++) {
            int row = mt * 16 + (lane >> 2) + half * 8;
            if (row >= PPT) continue;
#pragma unroll
            for (int tn = 0; tn < 4; tn++) {
                int col = warp * 32 + tn * 8 + ((lane & 3) << 1);
                hsh[row * 260 + col]     = gelu_f(acc[mt][tn][half * 2 + 0] + mb[col]);
                hsh[row * 260 + col + 1] = gelu_f(acc[mt][tn][half * 2 + 1] + mb[col + 1]);
            }
        }
    }
    __syncthreads();

    int d4 = tid & 63;
    int q0 = (tid >> 6) * 9;
    float4 accq[9];
#pragma unroll
    for (int q = 0; q < 9; q++) {
        float s = sb[q0 + q];
        accq[q] = make_float4(s, s, s, s);
    }
    for (int p = 0; p < PPT; p++) {
        float4 hv = *(const float4*)(hsh + p * 260 + 4 * d4);
#pragma unroll
        for (int q = 0; q < 9; q++) {
            float smv = sms[(q0 + q) * PPT + p];
            accq[q].x = fmaf(smv, hv.x, accq[q].x);
            accq[q].y = fmaf(smv, hv.y, accq[q].y);
            accq[q].z = fmaf(smv, hv.z, accq[q].z);
            accq[q].w = fmaf(smv, hv.w, accq[q].w);
        }
    }
    float* ho = g_h + (size_t)t * (PPT * CCH);
#pragma unroll
    for (int q = 0; q < 9; q++) {
        float4 o;
        o.x = f2tf32f(gelu_f(accq[q].x));
        o.y = f2tf32f(gelu_f(accq[q].y));
        o.z = f2tf32f(gelu_f(accq[q].z));
        o.w = f2tf32f(gelu_f(accq[q].w));
        *(float4*)(ho + (q0 + q) * CCH + 4 * d4) = o;
    }
}

// ---------------- layernorm ----------------
__global__ void ln_k(const float* __restrict__ x, const float* __restrict__ g,
                     const float* __restrict__ bb, float* __restrict__ y) {
    int t = blockIdx.x, tid = threadIdx.x;
    __shared__ float rs[4], rs2[4];
    const float* xr = x + (size_t)t * DIM;
    float v[4], s = 0.f, s2 = 0.f;
#pragma unroll
    for (int i = 0; i < 4; i++) { v[i] = xr[tid + 128 * i]; s += v[i]; s2 += v[i] * v[i]; }
#pragma unroll
    for (int o = 16; o; o >>= 1) {
        s  += __shfl_down_sync(0xffffffffu, s,  o);
        s2 += __shfl_down_sync(0xffffffffu, s2, o);
    }
    if ((tid & 31) == 0) { rs[tid >> 5] = s; rs2[tid >> 5] = s2; }
    __syncthreads();
    float ts = rs[0] + rs[1] + rs[2] + rs[3];
    float ts2 = rs2[0] + rs2[1] + rs2[2] + rs2[3];
    float mean = ts * (1.f / DIM);
    float var = ts2 * (1.f / DIM) - mean * mean;
    float rstd = rsqrtf(var + 1e-5f);
#pragma unroll
    for (int i = 0; i < 4; i++) {
        int k = tid + 128 * i;
        y[(size_t)t * DIM + k] = f2tf32f((v[i] - mean) * rstd * g[k] + bb[k]);
    }
}

// ---------------- attention v2 ----------------
__global__ void __launch_bounds__(128) attn_k() {
    extern __shared__ float asm_[];
    float* Ks  = asm_;
    float* Vs  = asm_ + 4096;
    float* scp = asm_ + 8192;

    int b = blockIdx.x, h = blockIdx.y;
    int tid = threadIdx.x;
    int q = tid & 63, half = tid >> 6;
    const float* base = g_qkv + (size_t)b * 64 * (3 * DIM);
    for (int i = tid; i < 64 * 64; i += 128) {
        int n = i >> 6, d2 = i & 63;
        Ks[i] = base[(size_t)n * (3 * DIM) + DIM     + h * 64 + d2];
        Vs[i] = base[(size_t)n * (3 * DIM) + 2 * DIM + h * 64 + d2];
    }
    float qreg[32];
    const float* qrow = base + (size_t)q * (3 * DIM) + h * 64 + half * 32;
#pragma unroll
    for (int j = 0; j < 32; j++) qreg[j] = qrow[j];
    __syncthreads();

#pragma unroll 4
    for (int k = 0; k < 64; k++) {
        float s = 0.f;
#pragma unroll
        for (int j = 0; j < 32; j++) s = fmaf(qreg[j], Ks[k * 64 + half * 32 + j], s);
        scp[half * 4096 + q * 64 + k] = s;
    }
    __syncthreads();

    if (half == 0) {
        float sc[64];
        float mx = -1e30f;
#pragma unroll
        for (int k = 0; k < 64; k++) {
            sc[k] = (scp[q * 64 + k] + scp[4096 + q * 64 + k]) * 0.125f;
            mx = fmaxf(mx, sc[k]);
        }
        float sum = 0.f;
#pragma unroll
        for (int k = 0; k < 64; k++) { sc[k] = expf(sc[k] - mx); sum += sc[k]; }
        float inv = 1.f / sum;
#pragma unroll
        for (int k = 0; k < 64; k++) scp[q * 64 + k] = sc[k] * inv;
    }
    __syncthreads();

    float* orow = g_attout + (size_t)(b * 64 + q) * DIM + h * 64 + half * 32;
#pragma unroll 4
    for (int d2 = 0; d2 < 32; d2++) {
        float o = 0.f;
#pragma unroll
        for (int k = 0; k < 64; k++) o = fmaf(scp[q * 64 + k], Vs[k * 64 + half * 32 + d2], o);
        orow[d2] = f2tf32f(o);
    }
}

// ---------------- streams / events ----------------
#define DSM8 (3 * (ASZ + 32 * 136) * 4)
#define DSM4 (3 * (ASZ + 32 * 72) * 4)
#define DSMA ((4096 + 4096 + 8192) * 4)
struct SfStreams {
    cudaStream_t s1, s2;
    cudaEvent_t e_root, e_pre, e_rpg2, e_inits, e_sample, e_wout, e_t2, e_proj, e_outi;
    SfStreams() {
        cudaStreamCreateWithFlags(&s1, cudaStreamNonBlocking);
        cudaStreamCreateWithFlags(&s2, cudaStreamNonBlocking);
        cudaEventCreateWithFlags(&e_root,   cudaEventDisableTiming);
        cudaEventCreateWithFlags(&e_pre,    cudaEventDisableTiming);
        cudaEventCreateWithFlags(&e_rpg2,   cudaEventDisableTiming);
        cudaEventCreateWithFlags(&e_inits,  cudaEventDisableTiming);
        cudaEventCreateWithFlags(&e_sample, cudaEventDisableTiming);
        cudaEventCreateWithFlags(&e_wout,   cudaEventDisableTiming);
        cudaEventCreateWithFlags(&e_t2,     cudaEventDisableTiming);
        cudaEventCreateWithFlags(&e_proj,   cudaEventDisableTiming);
        cudaEventCreateWithFlags(&e_outi,   cudaEventDisableTiming);
        cudaFuncSetAttribute(mma_gemm_t<8>, cudaFuncAttributeMaxDynamicSharedMemorySize, DSM8);
        cudaFuncSetAttribute(mma_gemm_t<4>, cudaFuncAttributeMaxDynamicSharedMemorySize, DSM4);
        cudaFuncSetAttribute(mixmma_k, cudaFuncAttributeMaxDynamicSharedMemorySize,
                             MIX_SMF * 4);
        cudaFuncSetAttribute(attn_k, cudaFuncAttributeMaxDynamicSharedMemorySize, DSMA);
    }
};
static SfStreams g_sf;

// ---------------- launch ----------------
extern "C" void kernel_launch(void* const* d_in, const int* in_sizes, int n_in,
                              void* d_out, int out_size) {
    const float* token_embed = (const float*)d_in[0];
    const float* token_roi   = (const float*)d_in[1];
    const float* img_feat    = (const float*)d_in[2];
    const float* ln_off_g    = (const float*)d_in[3];
    const float* ln_off_b    = (const float*)d_in[4];
    const float* w_off       = (const float*)d_in[5];
    const float* off_bias    = (const float*)d_in[6];
    const float* ln_pg_g     = (const float*)d_in[7];
    const float* ln_pg_b     = (const float*)d_in[8];
    const float* w_pg1       = (const float*)d_in[9];
    const float* b_pg1       = (const float*)d_in[10];
    const float* w_pg2       = (const float*)d_in[11];
    const float* b_pg2       = (const float*)d_in[12];
    const float* m_beta      = (const float*)d_in[13];
    const float* s_beta      = (const float*)d_in[14];
    const float* w_out       = (const float*)d_in[15];
    const float* b_out       = (const float*)d_in[16];
    const float* ln1_g       = (const float*)d_in[17];
    const float* ln1_b       = (const float*)d_in[18];
    const float* w_qkv       = (const float*)d_in[19];
    const float* b_qkv       = (const float*)d_in[20];
    const float* w_proj      = (const float*)d_in[21];
    const float* b_proj      = (const float*)d_in[22];
    const float* ln2_g       = (const float*)d_in[23];
    const float* ln2_b       = (const float*)d_in[24];
    const float* w_fc1       = (const float*)d_in[25];
    const float* b_fc1       = (const float*)d_in[26];
    const float* w_fc2       = (const float*)d_in[27];
    const float* b_fc2       = (const float*)d_in[28];
    float* out = (float*)d_out;

    void* p;
    cudaGetSymbolAddress(&p, g_hidden);  float* hidden = (float*)p;
    cudaGetSymbolAddress(&p, g_params);  float* params = (float*)p;
    cudaGetSymbolAddress(&p, g_h);       float* hbuf   = (float*)p;
    cudaGetSymbolAddress(&p, g_tok);     float* tok    = (float*)p;
    cudaGetSymbolAddress(&p, g_tok2);    float* tok2   = (float*)p;
    cudaGetSymbolAddress(&p, g_x);       float* xbuf   = (float*)p;
    cudaGetSymbolAddress(&p, g_qkv);     float* qkv    = (float*)p;
    cudaGetSymbolAddress(&p, g_attout);  float* attout = (float*)p;
    cudaGetSymbolAddress(&p, g_ff);      float* ff     = (float*)p;
    cudaGetSymbolAddress(&p, r_wpg2);    float* rwpg2  = (float*)p;
    cudaGetSymbolAddress(&p, r_wout);    float* rwout  = (float*)p;
    cudaGetSymbolAddress(&p, r_wqkv);    float* rwqkv  = (float*)p;
    cudaGetSymbolAddress(&p, r_wproj);   float* rwproj = (float*)p;
    cudaGetSymbolAddress(&p, r_wfc1);    float* rwfc1  = (float*)p;
    cudaGetSymbolAddress(&p, r_wfc2);    float* rwfc2  = (float*)p;

    const int DSMX = MIX_SMF * 4;
    cudaStream_t s0 = 0, s1 = g_sf.s1, s2 = g_sf.s2;

    // ---- fork ----
    cudaEventRecord(g_sf.e_root, s0);
    cudaStreamWaitEvent(s1, g_sf.e_root, 0);
    cudaStreamWaitEvent(s2, g_sf.e_root, 0);

    // s0: pre_k
    pre_k<<<TKN, 128, 0, s0>>>(token_embed, token_roi, ln_off_g, ln_off_b, w_off, off_bias,
                               ln_pg_g, ln_pg_b, w_pg1, b_pg1);
    cudaEventRecord(g_sf.e_pre, s0);

    // s1: wpg2 rounding, then rest
    round_pg2_k<<<(N4_0 + 255) / 256, 256, 0, s1>>>(w_pg2);
    cudaEventRecord(g_sf.e_rpg2, s1);
    round_rest_k<<<(R4_T + 255) / 256, 256, 0, s1>>>(w_out, w_qkv, w_proj, w_fc1, w_fc2);

    // s0: params GEMM (TN=8)
    cudaStreamWaitEvent(s0, g_sf.e_rpg2, 0);
    mma_gemm_t<8><<<dim3((TOTN + 127) / 128, TKN / 128, 1), 256, DSM8, s0>>>(
        hidden, rwpg2, b_pg2, params, TKN, TOTN, PGN, 1, 0);

    // s2: transpose, then sampling
    transpose_k<<<dim3((HGT * WID) / 32, CCH / 32, 8), 256, 0, s2>>>(img_feat);
    cudaStreamWaitEvent(s2, g_sf.e_pre, 0);
    sample_k<<<dim3(PPT, TKN), 64, 0, s2>>>();
    cudaEventRecord(g_sf.e_sample, s2);

    // s0: mixing
    cudaStreamWaitEvent(s0, g_sf.e_sample, 0);
    mixmma_k<<<TKN, 256, DSMX, s0>>>(m_beta, s_beta);

    // s1: inits
    init_k<<<(TKN * DIM + 255) / 256, 256, 0, s1>>>(token_embed, b_out, tok, TKN * DIM, DIM);
    init_k<<<(TKN * 3 * DIM + 255) / 256, 256, 0, s1>>>(nullptr, b_qkv, qkv, TKN * 3 * DIM, 3 * DIM);
    cudaEventRecord(g_sf.e_inits, s1);

    // s0: w_out GEMM (TN=4, splitK16)
    cudaStreamWaitEvent(s0, g_sf.e_inits, 0);
    mma_gemm_t<4><<<dim3(DIM / 64, TKN / 128, 16), 256, DSM4, s0>>>(
        hbuf, rwout, nullptr, tok, TKN, DIM, PPT * CCH, 0, 0);
    cudaEventRecord(g_sf.e_wout, s0);

    // s1: init_tok2 in parallel
    cudaStreamWaitEvent(s1, g_sf.e_wout, 0);
    init_k<<<(TKN * DIM + 255) / 256, 256, 0, s1>>>(tok, b_proj, tok2, TKN * DIM, DIM);
    cudaEventRecord(g_sf.e_t2, s1);

    // s0: LN1 -> qkv -> attention
    ln_k<<<TKN, 128, 0, s0>>>(tok, ln1_g, ln1_b, xbuf);
    mma_gemm_t<4><<<dim3((3 * DIM) / 64, TKN / 128, 4), 256, DSM4, s0>>>(
        xbuf, rwqkv, nullptr, qkv, TKN, 3 * DIM, DIM, 0, 0);
    attn_k<<<dim3(8, 8), 128, DSMA, s0>>>();
    // s0: proj
    cudaStreamWaitEvent(s0, g_sf.e_t2, 0);
    mma_gemm_t<4><<<dim3(DIM / 64, TKN / 128, 8), 256, DSM4, s0>>>(
        attout, rwproj, nullptr, tok2, TKN, DIM, DIM, 0, 0);
    cudaEventRecord(g_sf.e_proj, s0);

    // s2: init_out in parallel
    cudaStreamWaitEvent(s2, g_sf.e_proj, 0);
    init_k<<<(TKN * DIM + 255) / 256, 256, 0, s2>>>(tok2, b_fc2, out, TKN * DIM, DIM);
    cudaEventRecord(g_sf.e_outi, s2);

    // s0: LN2 -> fc1 (fused bias+gelu) -> fc2
    ln_k<<<TKN, 128, 0, s0>>>(tok2, ln2_g, ln2_b, xbuf);
    mma_gemm_t<4><<<dim3((4 * DIM) / 64, TKN / 128, 1), 256, DSM4, s0>>>(
        xbuf, rwfc1, b_fc1, ff, TKN, 4 * DIM, DIM, 0, 1);
    cudaStreamWaitEvent(s0, g_sf.e_outi, 0);
    mma_gemm_t<4><<<dim3(DIM / 64, TKN / 128, 16), 256, DSM4, s0>>>(
        ff, rwfc2, nullptr, out, TKN, DIM, 4 * DIM, 0, 0);
}

// round 13
// speedup vs baseline: 1.1312x; 1.0566x over previous
#include <cuda_runtime.h>
#include <math.h>
#include <stdint.h>

// ---------------- constants ----------------
#define TKN 512
#define DIM 512
#define CCH 256
#define HGT 128
#define WID 128
#define PPT 36
#define PGN 128
#define TOTN 66832
#define CC2 65536

// ---------------- scratch ----------------
__device__ float g_imgT[8 * HGT * WID * CCH];
__device__ float g_hidden[TKN * PGN];
__device__ float g_grid[TKN * PPT * 2];
__device__ float g_params[(size_t)TKN * TOTN];
__device__ float g_sampled[TKN * PPT * CCH];
__device__ float g_h[TKN * PPT * CCH];
__device__ float g_tok[TKN * DIM];
__device__ float g_tok2[TKN * DIM];
__device__ float g_x[TKN * DIM];
__device__ float g_qkv[TKN * 3 * DIM];
__device__ float g_attout[TKN * DIM];
__device__ float g_ff[TKN * 4 * DIM];

__device__ __forceinline__ float gelu_f(float x) {
    return 0.5f * x * (1.0f + erff(x * 0.70710678118654752440f));
}
__device__ __forceinline__ float f2tf32f(float x) {
    uint32_t r;
    asm("cvt.rna.tf32.f32 %0, %1;" : "=r"(r) : "f"(x));
    return __uint_as_float(r);
}
__device__ __forceinline__ void red2f(float* p, float a, float b) {
    asm volatile("red.global.add.v2.f32 [%0], {%1, %2};"
                 :: "l"(p), "f"(a), "f"(b) : "memory");
}

// ---------------- img transpose ----------------
__global__ void transpose_k(const float* __restrict__ in) {
    __shared__ float tile[32][33];
    int b = blockIdx.z;
    int s0 = blockIdx.x * 32;
    int c0 = blockIdx.y * 32;
    const float* ib = in + (size_t)b * CCH * HGT * WID;
    float* ob = g_imgT + (size_t)b * HGT * WID * CCH;
    int tid = threadIdx.x;
    {
        int c = tid >> 3, s4 = tid & 7;
        float4 v = *(const float4*)(ib + (size_t)(c0 + c) * (HGT * WID) + s0 + 4 * s4);
        tile[4 * s4 + 0][c] = v.x;
        tile[4 * s4 + 1][c] = v.y;
        tile[4 * s4 + 2][c] = v.z;
        tile[4 * s4 + 3][c] = v.w;
    }
    __syncthreads();
    {
        int g = tid & 7, s = tid >> 3;
        float4 v;
        v.x = tile[s][4 * g + 0];
        v.y = tile[s][4 * g + 1];
        v.z = tile[s][4 * g + 2];
        v.w = tile[s][4 * g + 3];
        *(float4*)(ob + (size_t)(s0 + s) * CCH + c0 + 4 * g) = v;
    }
}

// ---------------- per-token pre ----------------
__global__ void pre_k(const float* __restrict__ x, const float* __restrict__ roi,
                      const float* __restrict__ g_off, const float* __restrict__ b_off,
                      const float* __restrict__ w_off, const float* __restrict__ off_bias,
                      const float* __restrict__ g_pg, const float* __restrict__ b_pg,
                      const float* __restrict__ w_pg1, const float* __restrict__ b_pg1) {
    int t = blockIdx.x;
    int tid = threadIdx.x;
    __shared__ float xoff[DIM], xpg[DIM], offs[72];
    __shared__ float rs[4], rs2[4], stats[4];

    const float* xr = x + (size_t)t * DIM;
    float v[4], s = 0.f, s2 = 0.f;
#pragma unroll
    for (int i = 0; i < 4; i++) { v[i] = xr[tid + 128 * i]; s += v[i]; s2 += v[i] * v[i]; }
#pragma unroll
    for (int o = 16; o; o >>= 1) {
        s  += __shfl_down_sync(0xffffffffu, s,  o);
        s2 += __shfl_down_sync(0xffffffffu, s2, o);
    }
    if ((tid & 31) == 0) { rs[tid >> 5] = s; rs2[tid >> 5] = s2; }
    __syncthreads();
    float ts = rs[0] + rs[1] + rs[2] + rs[3];
    float ts2 = rs2[0] + rs2[1] + rs2[2] + rs2[3];
    float mean = ts * (1.f / DIM);
    float var = ts2 * (1.f / DIM) - mean * mean;
    float rstd = rsqrtf(var + 1e-5f);
#pragma unroll
    for (int i = 0; i < 4; i++) {
        int k = tid + 128 * i;
        float xn = (v[i] - mean) * rstd;
        xoff[k] = xn * g_off[k] + b_off[k];
        xpg[k]  = xn * g_pg[k]  + b_pg[k];
    }
    __syncthreads();

    {
        float h = b_pg1[tid];
        for (int k = 0; k < DIM; k++) h = fmaf(xpg[k], w_pg1[k * PGN + tid], h);
        g_hidden[t * PGN + tid] = f2tf32f(h);
    }
    if (tid < 72) {
        float o = off_bias[tid];
        for (int k = 0; k < DIM; k++) o = fmaf(xoff[k], w_off[k * 72 + tid], o);
        offs[tid] = o;
    }
    __syncthreads();
    if (tid < 2) {
        float mu = 0.f;
        for (int p = 0; p < PPT; p++) mu += offs[p * 2 + tid];
        mu *= (1.f / PPT);
        float vv = 0.f;
        for (int p = 0; p < PPT; p++) { float d = offs[p * 2 + tid] - mu; vv += d * d; }
        vv *= (1.f / (PPT - 1));
        stats[tid * 2] = mu;
        stats[tid * 2 + 1] = sqrtf(vv) + 1e-5f;
    }
    __syncthreads();
    if (tid < 72) {
        int coord = tid & 1, p = tid >> 1;
        float mu = stats[coord * 2], sd = stats[coord * 2 + 1];
        float on = (offs[tid] - mu) / (3.f * sd);
        float tl = roi[t * 4 + coord], br = roi[t * 4 + 2 + coord];
        float xy = 0.5f * (tl + br), wh = br - tl;
        float pt = xy + on * wh;
        g_grid[(t * PPT + p) * 2 + coord] = pt * 2.f - 1.f;
    }
}

// ---------------- bilinear grid sample ----------------
__global__ void sample_k() {
    int p = blockIdx.x, t = blockIdx.y;
    int c4 = threadIdx.x << 2;
    int b = t >> 6;
    float gx = g_grid[(t * PPT + p) * 2 + 0];
    float gy = g_grid[(t * PPT + p) * 2 + 1];
    float x = ((gx + 1.f) * WID - 1.f) * 0.5f;
    float y = ((gy + 1.f) * HGT - 1.f) * 0.5f;
    float x0f = floorf(x), y0f = floorf(y);
    float wx = x - x0f, wy = y - y0f;
    int x0 = min(max((int)x0f, 0), WID - 1);
    int x1 = min(max((int)x0f + 1, 0), WID - 1);
    int y0 = min(max((int)y0f, 0), HGT - 1);
    int y1 = min(max((int)y0f + 1, 0), HGT - 1);
    const float* ib = g_imgT + (size_t)b * HGT * WID * CCH;
    float4 v00 = *(const float4*)(ib + (size_t)(y0 * WID + x0) * CCH + c4);
    float4 v01 = *(const float4*)(ib + (size_t)(y0 * WID + x1) * CCH + c4);
    float4 v10 = *(const float4*)(ib + (size_t)(y1 * WID + x0) * CCH + c4);
    float4 v11 = *(const float4*)(ib + (size_t)(y1 * WID + x1) * CCH + c4);
    float w00 = (1.f - wx) * (1.f - wy), w01 = wx * (1.f - wy);
    float w10 = (1.f - wx) * wy,         w11 = wx * wy;
    float4 o;
    o.x = v00.x * w00 + v01.x * w01 + v10.x * w10 + v11.x * w11;
    o.y = v00.y * w00 + v01.y * w01 + v10.y * w10 + v11.y * w11;
    o.z = v00.z * w00 + v01.z * w01 + v10.z * w10 + v11.z * w11;
    o.w = v00.w * w00 + v01.w * w01 + v10.w * w10 + v11.w * w11;
    *(float4*)(g_sampled + ((size_t)t * PPT + p) * CCH + c4) = o;
}

// ---------------- cp.async helpers ----------------
__device__ __forceinline__ void cpa16(uint32_t dst, const void* src, bool pred) {
    int sz = pred ? 16 : 0;
    asm volatile("cp.async.cg.shared.global [%0], [%1], 16, %2;"
                 :: "r"(dst), "l"(src), "r"(sz));
}
__device__ __forceinline__ void cpa_commit() {
    asm volatile("cp.async.commit_group;");
}
__device__ __forceinline__ uint32_t smem_u32(const void* p) {
    uint32_t a;
    asm("{ .reg .u64 t; cvta.to.shared.u64 t, %1; cvt.u32.u64 %0, t; }" : "=r"(a) : "l"(p));
    return a;
}

// ---------------- templated tf32 GEMM: 3-buffer pipeline, 1 barrier/ktile ----------------
// B operand may be raw fp32: tensor core reads the tf32 bit subset (truncation).
#define ASZ 4608
template <int TN>
__global__ void __launch_bounds__(256)
mma_gemm_t(const float* __restrict__ A, const float* __restrict__ Bm,
           const float* __restrict__ bias, float* __restrict__ C,
           int M, int N, int K, int rnd, int act) {
    constexpr int BN   = TN * 16;
    constexpr int BSTR = BN + 8;
    constexpr int BSZf = 32 * BSTR;
    constexpr int STGf = ASZ + BSZf;
    constexpr int BIT  = BN / 32;
    constexpr int BQ   = BN / 4;

    extern __shared__ float smf[];
    uint32_t sbase = smem_u32(smf);

    int tid = threadIdx.x;
    int warp = tid >> 5, lane = tid & 31;
    int wr = (warp >> 1) * 32;
    int wc = (warp & 1) * (TN * 8);
    int bR = blockIdx.y * 128, bC = blockIdx.x * BN;
    int nz = gridDim.z;
    int Kc = K / nz;
    int kbeg = blockIdx.z * Kc;
    int ntiles = Kc >> 5;

    float acc[2][TN][4];
#pragma unroll
    for (int a = 0; a < 2; a++)
#pragma unroll
        for (int b = 0; b < TN; b++)
#pragma unroll
            for (int c = 0; c < 4; c++) acc[a][b][c] = 0.f;

    int ar[4], ac[4];
#pragma unroll
    for (int i = 0; i < 4; i++) {
        int f = tid + (i << 8);
        ar[i] = f >> 3;  ac[i] = (f & 7) << 2;
    }
    int br_[BIT], bc_[BIT];
#pragma unroll
    for (int i = 0; i < BIT; i++) {
        int f = tid + (i << 8);
        br_[i] = f / BQ; bc_[i] = (f % BQ) << 2;
    }

    auto issue = [&](int t, int stage) {
        int k0 = kbeg + (t << 5);
        uint32_t sa = sbase + stage * (STGf * 4);
#pragma unroll
        for (int i = 0; i < 4; i++) {
            cpa16(sa + (ar[i] * 36 + ac[i]) * 4,
                  A + (size_t)(bR + ar[i]) * K + k0 + ac[i], true);
        }
        uint32_t sb = sa + ASZ * 4;
#pragma unroll
        for (int i = 0; i < BIT; i++) {
            int gc = bC + bc_[i];
            cpa16(sb + (br_[i] * BSTR + bc_[i]) * 4,
                  Bm + (size_t)(k0 + br_[i]) * N + gc, gc < N);
        }
        cpa_commit();
    };

    issue(0, 0);
    if (ntiles > 1) issue(1, 1);
    int rd = 0;
    int wrb = 2;
    for (int t = 0; t < ntiles; t++) {
        if (t + 1 < ntiles) {
            asm volatile("cp.async.wait_group 1;");
        } else {
            asm volatile("cp.async.wait_group 0;");
        }
        __syncthreads();
        if (t + 2 < ntiles) {
            issue(t + 2, wrb);
            wrb = (wrb == 2) ? 0 : wrb + 1;
        }
        const uint32_t* As = (const uint32_t*)(smf + rd * STGf);
        const uint32_t* Bs = As + ASZ;
        rd = (rd == 2) ? 0 : rd + 1;
#pragma unroll
        for (int k8 = 0; k8 < 4; k8++) {
            int kk = k8 << 3;
            uint32_t afr[2][4];
#pragma unroll
            for (int tm = 0; tm < 2; tm++) {
                int r = wr + tm * 16 + (lane >> 2);
                int c = kk + (lane & 3);
                afr[tm][0] = As[r * 36 + c];
                afr[tm][1] = As[(r + 8) * 36 + c];
                afr[tm][2] = As[r * 36 + c + 4];
                afr[tm][3] = As[(r + 8) * 36 + c + 4];
            }
#pragma unroll
            for (int tn = 0; tn < TN; tn++) {
                int col = wc + tn * 8 + (lane >> 2);
                uint32_t b0 = Bs[(kk + (lane & 3)) * BSTR + col];
                uint32_t b1 = Bs[(kk + (lane & 3) + 4) * BSTR + col];
#pragma unroll
                for (int tm = 0; tm < 2; tm++) {
                    asm volatile(
                        "mma.sync.aligned.m16n8k8.row.col.f32.tf32.tf32.f32 "
                        "{%0,%1,%2,%3}, {%4,%5,%6,%7}, {%8,%9}, {%0,%1,%2,%3};"
                        : "+f"(acc[tm][tn][0]), "+f"(acc[tm][tn][1]),
                          "+f"(acc[tm][tn][2]), "+f"(acc[tm][tn][3])
                        : "r"(afr[tm][0]), "r"(afr[tm][1]),
                          "r"(afr[tm][2]), "r"(afr[tm][3]),
                          "r"(b0), "r"(b1));
                }
            }
        }
    }

    if (nz == 1) {
#pragma unroll
        for (int tm = 0; tm < 2; tm++) {
            int row = bR + wr + tm * 16 + (lane >> 2);
#pragma unroll
            for (int tn = 0; tn < TN; tn++) {
                int col = bC + wc + tn * 8 + ((lane & 3) << 1);
                if (col >= N) continue;
                float bv0 = 0.f, bv1 = 0.f;
                if (bias) { bv0 = bias[col]; bv1 = bias[col + 1]; }
                float o0 = acc[tm][tn][0] + bv0, o1 = acc[tm][tn][1] + bv1;
                float o2 = acc[tm][tn][2] + bv0, o3 = acc[tm][tn][3] + bv1;
                if (act) {
                    o0 = gelu_f(o0); o1 = gelu_f(o1);
                    o2 = gelu_f(o2); o3 = gelu_f(o3);
                }
                if (rnd | act) {
                    o0 = f2tf32f(o0); o1 = f2tf32f(o1);
                    o2 = f2tf32f(o2); o3 = f2tf32f(o3);
                }
                *(float2*)(&C[(size_t)row * N + col])       = make_float2(o0, o1);
                *(float2*)(&C[(size_t)(row + 8) * N + col]) = make_float2(o2, o3);
            }
        }
    } else {
#pragma unroll
        for (int tm = 0; tm < 2; tm++) {
            int row = bR + wr + tm * 16 + (lane >> 2);
#pragma unroll
            for (int tn = 0; tn < TN; tn++) {
                int col = bC + wc + tn * 8 + ((lane & 3) << 1);
                red2f(&C[(size_t)row * N + col], acc[tm][tn][0], acc[tm][tn][1]);
                red2f(&C[(size_t)(row + 8) * N + col], acc[tm][tn][2], acc[tm][tn][3]);
            }
        }
    }
}

// ---------------- init ----------------
__global__ void init_k(const float* __restrict__ resid, const float* __restrict__ bias,
                       float* __restrict__ C, int n, int N) {
    int i = blockIdx.x * 256 + threadIdx.x;
    if (i < n) {
        int col = i % N;
        C[i] = (resid ? resid[i] : 0.f) + bias[col];
    }
}

// ---------------- tensor-core per-token mixing ----------------
#define MIX_ASTR 260
#define MIX_BSTR 264
#define MIX_AF (48 * MIX_ASTR)
#define MIX_BF (32 * MIX_BSTR)
#define MIX_SMF (MIX_AF + 2 * MIX_BF + 1296)
__global__ void __launch_bounds__(256)
mixmma_k(const float* __restrict__ mb, const float* __restrict__ sb) {
    extern __shared__ float smf[];
    float* Aa  = smf;
    float* Bb  = smf + MIX_AF;
    float* sms = smf + MIX_AF + 2 * MIX_BF;
    uint32_t sbase = smem_u32(smf);

    int t = blockIdx.x, tid = threadIdx.x;
    int warp = tid >> 5, lane = tid & 31;
    const float* pt = g_params + (size_t)t * TOTN;

    for (int i = tid; i < 12 * MIX_ASTR; i += 256) Aa[36 * MIX_ASTR + i] = 0.f;
    const float4* sp4 = (const float4*)(g_sampled + (size_t)t * (PPT * CCH));
    for (int i = tid; i < PPT * CCH / 4; i += 256) {
        float4 v = sp4[i];
        int r = i >> 6, c = (i & 63) << 2;
        float* d = Aa + r * MIX_ASTR + c;
        d[0] = f2tf32f(v.x); d[1] = f2tf32f(v.y);
        d[2] = f2tf32f(v.z); d[3] = f2tf32f(v.w);
    }
    for (int i = tid; i < PPT * PPT; i += 256) sms[i] = pt[CC2 + i];

    uint32_t bB = sbase + MIX_AF * 4;
    auto issue = [&](int ch, int stg) {
        const float* src = pt + ch * 32 * 256;
        uint32_t dst = bB + stg * (MIX_BF * 4);
#pragma unroll
        for (int i = 0; i < 8; i++) {
            int e = tid + (i << 8);
            int r = e >> 6, c4 = (e & 63) << 2;
            cpa16(dst + (r * MIX_BSTR + c4) * 4, src + r * 256 + c4, true);
        }
        cpa_commit();
    };

    float acc[3][4][4];
#pragma unroll
    for (int a = 0; a < 3; a++)
#pragma unroll
        for (int b = 0; b < 4; b++)
#pragma unroll
            for (int c = 0; c < 4; c++) acc[a][b][c] = 0.f;

    issue(0, 0);
    for (int ch = 0; ch < 8; ch++) {
        if (ch + 1 < 8) {
            issue(ch + 1, (ch + 1) & 1);
            asm volatile("cp.async.wait_group 1;");
        } else {
            asm volatile("cp.async.wait_group 0;");
        }
        __syncthreads();
        const uint32_t* As = (const uint32_t*)Aa;
        const uint32_t* Bs = (const uint32_t*)(Bb + (ch & 1) * MIX_BF);
#pragma unroll
        for (int k8 = 0; k8 < 4; k8++) {
            int kk = (ch << 5) + (k8 << 3);
            int kb = k8 << 3;
            uint32_t afr[3][4];
#pragma unroll
            for (int mt = 0; mt < 3; mt++) {
                int r = mt * 16 + (lane >> 2);
                int c = kk + (lane & 3);
                afr[mt][0] = As[r * MIX_ASTR + c];
                afr[mt][1] = As[(r + 8) * MIX_ASTR + c];
                afr[mt][2] = As[r * MIX_ASTR + c + 4];
                afr[mt][3] = As[(r + 8) * MIX_ASTR + c + 4];
            }
#pragma unroll
            for (int tn = 0; tn < 4; tn++) {
                int col = warp * 32 + tn * 8 + (lane >> 2);
                uint32_t b0 = Bs[(kb + (lane & 3)) * MIX_BSTR + col];
                uint32_t b1 = Bs[(kb + (lane & 3) + 4) * MIX_BSTR + col];
#pragma unroll
                for (int mt = 0; mt < 3; mt++) {
                    asm volatile(
                        "mma.sync.aligned.m16n8k8.row.col.f32.tf32.tf32.f32 "
                        "{%0,%1,%2,%3}, {%4,%5,%6,%7}, {%8,%9}, {%0,%1,%2,%3};"
                        : "+f"(acc[mt][tn][0]), "+f"(acc[mt][tn][1]),
                          "+f"(acc[mt][tn][2]), "+f"(acc[mt][tn][3])
                        : "r"(afr[mt][0]), "r"(afr[mt][1]),
                          "r"(afr[mt][2]), "r"(afr[mt][3]),
                          "r"(b0), "r"(b1));
                }
            }
        }
        __syncthreads();
    }

    float* hsh = Bb;
#pragma unroll
    for (int mt = 0; mt < 3; mt++) {
#pragma unroll
        for (int half = 0; half < 2; half++) {
            int row = mt * 16 + (lane >> 2) + half * 8;
            if (row >= PPT) continue;
#pragma unroll
            for (int tn = 0; tn < 4; tn++) {
                int col = warp * 32 + tn * 8 + ((lane & 3) << 1);
                hsh[row * 260 + col]     = gelu_f(acc[mt][tn][half * 2 + 0] + mb[col]);
                hsh[row * 260 + col + 1] = gelu_f(acc[mt][tn][half * 2 + 1] + mb[col + 1]);
            }
        }
    }
    __syncthreads();

    int d4 = tid & 63;
    int q0 = (tid >> 6) * 9;
    float4 accq[9];
#pragma unroll
    for (int q = 0; q < 9; q++) {
        float s = sb[q0 + q];
        accq[q] = make_float4(s, s, s, s);
    }
    for (int p = 0; p < PPT; p++) {
        float4 hv = *(const float4*)(hsh + p * 260 + 4 * d4);
#pragma unroll
        for (int q = 0; q < 9; q++) {
            float smv = sms[(q0 + q) * PPT + p];
            accq[q].x = fmaf(smv, hv.x, accq[q].x);
            accq[q].y = fmaf(smv, hv.y, accq[q].y);
            accq[q].z = fmaf(smv, hv.z, accq[q].z);
            accq[q].w = fmaf(smv, hv.w, accq[q].w);
        }
    }
    float* ho = g_h + (size_t)t * (PPT * CCH);
#pragma unroll
    for (int q = 0; q < 9; q++) {
        float4 o;
        o.x = f2tf32f(gelu_f(accq[q].x));
        o.y = f2tf32f(gelu_f(accq[q].y));
        o.z = f2tf32f(gelu_f(accq[q].z));
        o.w = f2tf32f(gelu_f(accq[q].w));
        *(float4*)(ho + (q0 + q) * CCH + 4 * d4) = o;
    }
}

// ---------------- layernorm ----------------
__global__ void ln_k(const float* __restrict__ x, const float* __restrict__ g,
                     const float* __restrict__ bb, float* __restrict__ y) {
    int t = blockIdx.x, tid = threadIdx.x;
    __shared__ float rs[4], rs2[4];
    const float* xr = x + (size_t)t * DIM;
    float v[4], s = 0.f, s2 = 0.f;
#pragma unroll
    for (int i = 0; i < 4; i++) { v[i] = xr[tid + 128 * i]; s += v[i]; s2 += v[i] * v[i]; }
#pragma unroll
    for (int o = 16; o; o >>= 1) {
        s  += __shfl_down_sync(0xffffffffu, s,  o);
        s2 += __shfl_down_sync(0xffffffffu, s2, o);
    }
    if ((tid & 31) == 0) { rs[tid >> 5] = s; rs2[tid >> 5] = s2; }
    __syncthreads();
    float ts = rs[0] + rs[1] + rs[2] + rs[3];
    float ts2 = rs2[0] + rs2[1] + rs2[2] + rs2[3];
    float mean = ts * (1.f / DIM);
    float var = ts2 * (1.f / DIM) - mean * mean;
    float rstd = rsqrtf(var + 1e-5f);
#pragma unroll
    for (int i = 0; i < 4; i++) {
        int k = tid + 128 * i;
        y[(size_t)t * DIM + k] = f2tf32f((v[i] - mean) * rstd * g[k] + bb[k]);
    }
}

// ---------------- attention v2 ----------------
__global__ void __launch_bounds__(128) attn_k() {
    extern __shared__ float asm_[];
    float* Ks  = asm_;
    float* Vs  = asm_ + 4096;
    float* scp = asm_ + 8192;

    int b = blockIdx.x, h = blockIdx.y;
    int tid = threadIdx.x;
    int q = tid & 63, half = tid >> 6;
    const float* base = g_qkv + (size_t)b * 64 * (3 * DIM);
    for (int i = tid; i < 64 * 64; i += 128) {
        int n = i >> 6, d2 = i & 63;
        Ks[i] = base[(size_t)n * (3 * DIM) + DIM     + h * 64 + d2];
        Vs[i] = base[(size_t)n * (3 * DIM) + 2 * DIM + h * 64 + d2];
    }
    float qreg[32];
    const float* qrow = base + (size_t)q * (3 * DIM) + h * 64 + half * 32;
#pragma unroll
    for (int j = 0; j < 32; j++) qreg[j] = qrow[j];
    __syncthreads();

#pragma unroll 4
    for (int k = 0; k < 64; k++) {
        float s = 0.f;
#pragma unroll
        for (int j = 0; j < 32; j++) s = fmaf(qreg[j], Ks[k * 64 + half * 32 + j], s);
        scp[half * 4096 + q * 64 + k] = s;
    }
    __syncthreads();

    if (half == 0) {
        float sc[64];
        float mx = -1e30f;
#pragma unroll
        for (int k = 0; k < 64; k++) {
            sc[k] = (scp[q * 64 + k] + scp[4096 + q * 64 + k]) * 0.125f;
            mx = fmaxf(mx, sc[k]);
        }
        float sum = 0.f;
#pragma unroll
        for (int k = 0; k < 64; k++) { sc[k] = expf(sc[k] - mx); sum += sc[k]; }
        float inv = 1.f / sum;
#pragma unroll
        for (int k = 0; k < 64; k++) scp[q * 64 + k] = sc[k] * inv;
    }
    __syncthreads();

    float* orow = g_attout + (size_t)(b * 64 + q) * DIM + h * 64 + half * 32;
#pragma unroll 4
    for (int d2 = 0; d2 < 32; d2++) {
        float o = 0.f;
#pragma unroll
        for (int k = 0; k < 64; k++) o = fmaf(scp[q * 64 + k], Vs[k * 64 + half * 32 + d2], o);
        orow[d2] = f2tf32f(o);
    }
}

// ---------------- streams / events ----------------
#define DSM8 (3 * (ASZ + 32 * 136) * 4)
#define DSM4 (3 * (ASZ + 32 * 72) * 4)
#define DSMA ((4096 + 4096 + 8192) * 4)
struct SfStreams {
    cudaStream_t s1, s2;
    cudaEvent_t e_root, e_pre, e_inits, e_sample, e_wout, e_t2, e_proj, e_outi;
    SfStreams() {
        cudaStreamCreateWithFlags(&s1, cudaStreamNonBlocking);
        cudaStreamCreateWithFlags(&s2, cudaStreamNonBlocking);
        cudaEventCreateWithFlags(&e_root,   cudaEventDisableTiming);
        cudaEventCreateWithFlags(&e_pre,    cudaEventDisableTiming);
        cudaEventCreateWithFlags(&e_inits,  cudaEventDisableTiming);
        cudaEventCreateWithFlags(&e_sample, cudaEventDisableTiming);
        cudaEventCreateWithFlags(&e_wout,   cudaEventDisableTiming);
        cudaEventCreateWithFlags(&e_t2,     cudaEventDisableTiming);
        cudaEventCreateWithFlags(&e_proj,   cudaEventDisableTiming);
        cudaEventCreateWithFlags(&e_outi,   cudaEventDisableTiming);
        cudaFuncSetAttribute(mma_gemm_t<8>, cudaFuncAttributeMaxDynamicSharedMemorySize, DSM8);
        cudaFuncSetAttribute(mma_gemm_t<4>, cudaFuncAttributeMaxDynamicSharedMemorySize, DSM4);
        cudaFuncSetAttribute(mixmma_k, cudaFuncAttributeMaxDynamicSharedMemorySize,
                             MIX_SMF * 4);
        cudaFuncSetAttribute(attn_k, cudaFuncAttributeMaxDynamicSharedMemorySize, DSMA);
    }
};
static SfStreams g_sf;

// ---------------- launch ----------------
extern "C" void kernel_launch(void* const* d_in, const int* in_sizes, int n_in,
                              void* d_out, int out_size) {
    const float* token_embed = (const float*)d_in[0];
    const float* token_roi   = (const float*)d_in[1];
    const float* img_feat    = (const float*)d_in[2];
    const float* ln_off_g    = (const float*)d_in[3];
    const float* ln_off_b    = (const float*)d_in[4];
    const float* w_off       = (const float*)d_in[5];
    const float* off_bias    = (const float*)d_in[6];
    const float* ln_pg_g     = (const float*)d_in[7];
    const float* ln_pg_b     = (const float*)d_in[8];
    const float* w_pg1       = (const float*)d_in[9];
    const float* b_pg1       = (const float*)d_in[10];
    const float* w_pg2       = (const float*)d_in[11];
    const float* b_pg2       = (const float*)d_in[12];
    const float* m_beta      = (const float*)d_in[13];
    const float* s_beta      = (const float*)d_in[14];
    const float* w_out       = (const float*)d_in[15];
    const float* b_out       = (const float*)d_in[16];
    const float* ln1_g       = (const float*)d_in[17];
    const float* ln1_b       = (const float*)d_in[18];
    const float* w_qkv       = (const float*)d_in[19];
    const float* b_qkv       = (const float*)d_in[20];
    const float* w_proj      = (const float*)d_in[21];
    const float* b_proj      = (const float*)d_in[22];
    const float* ln2_g       = (const float*)d_in[23];
    const float* ln2_b       = (const float*)d_in[24];
    const float* w_fc1       = (const float*)d_in[25];
    const float* b_fc1       = (const float*)d_in[26];
    const float* w_fc2       = (const float*)d_in[27];
    const float* b_fc2       = (const float*)d_in[28];
    float* out = (float*)d_out;

    void* p;
    cudaGetSymbolAddress(&p, g_hidden);  float* hidden = (float*)p;
    cudaGetSymbolAddress(&p, g_params);  float* params = (float*)p;
    cudaGetSymbolAddress(&p, g_h);       float* hbuf   = (float*)p;
    cudaGetSymbolAddress(&p, g_tok);     float* tok    = (float*)p;
    cudaGetSymbolAddress(&p, g_tok2);    float* tok2   = (float*)p;
    cudaGetSymbolAddress(&p, g_x);       float* xbuf   = (float*)p;
    cudaGetSymbolAddress(&p, g_qkv);     float* qkv    = (float*)p;
    cudaGetSymbolAddress(&p, g_attout);  float* attout = (float*)p;
    cudaGetSymbolAddress(&p, g_ff);      float* ff     = (float*)p;

    const int DSMX = MIX_SMF * 4;
    cudaStream_t s0 = 0, s1 = g_sf.s1, s2 = g_sf.s2;

    // ---- fork ----
    cudaEventRecord(g_sf.e_root, s0);
    cudaStreamWaitEvent(s1, g_sf.e_root, 0);
    cudaStreamWaitEvent(s2, g_sf.e_root, 0);

    // s0: pre_k -> params GEMM immediately (raw w_pg2; HW truncates B to tf32)
    pre_k<<<TKN, 128, 0, s0>>>(token_embed, token_roi, ln_off_g, ln_off_b, w_off, off_bias,
                               ln_pg_g, ln_pg_b, w_pg1, b_pg1);
    cudaEventRecord(g_sf.e_pre, s0);
    mma_gemm_t<8><<<dim3((TOTN + 127) / 128, TKN / 128, 1), 256, DSM8, s0>>>(
        hidden, w_pg2, b_pg2, params, TKN, TOTN, PGN, 1, 0);

    // s1: inits (independent of everything but inputs)
    init_k<<<(TKN * DIM + 255) / 256, 256, 0, s1>>>(token_embed, b_out, tok, TKN * DIM, DIM);
    init_k<<<(TKN * 3 * DIM + 255) / 256, 256, 0, s1>>>(nullptr, b_qkv, qkv, TKN * 3 * DIM, 3 * DIM);
    cudaEventRecord(g_sf.e_inits, s1);

    // s2: transpose, then sampling
    transpose_k<<<dim3((HGT * WID) / 32, CCH / 32, 8), 256, 0, s2>>>(img_feat);
    cudaStreamWaitEvent(s2, g_sf.e_pre, 0);
    sample_k<<<dim3(PPT, TKN), 64, 0, s2>>>();
    cudaEventRecord(g_sf.e_sample, s2);

    // s0: mixing
    cudaStreamWaitEvent(s0, g_sf.e_sample, 0);
    mixmma_k<<<TKN, 256, DSMX, s0>>>(m_beta, s_beta);

    // s0: w_out GEMM (TN=4, splitK16; raw w_out)
    cudaStreamWaitEvent(s0, g_sf.e_inits, 0);
    mma_gemm_t<4><<<dim3(DIM / 64, TKN / 128, 16), 256, DSM4, s0>>>(
        hbuf, w_out, nullptr, tok, TKN, DIM, PPT * CCH, 0, 0);
    cudaEventRecord(g_sf.e_wout, s0);

    // s1: init_tok2 in parallel
    cudaStreamWaitEvent(s1, g_sf.e_wout, 0);
    init_k<<<(TKN * DIM + 255) / 256, 256, 0, s1>>>(tok, b_proj, tok2, TKN * DIM, DIM);
    cudaEventRecord(g_sf.e_t2, s1);

    // s0: LN1 -> qkv -> attention
    ln_k<<<TKN, 128, 0, s0>>>(tok, ln1_g, ln1_b, xbuf);
    mma_gemm_t<4><<<dim3((3 * DIM) / 64, TKN / 128, 4), 256, DSM4, s0>>>(
        xbuf, w_qkv, nullptr, qkv, TKN, 3 * DIM, DIM, 0, 0);
    attn_k<<<dim3(8, 8), 128, DSMA, s0>>>();
    // s0: proj
    cudaStreamWaitEvent(s0, g_sf.e_t2, 0);
    mma_gemm_t<4><<<dim3(DIM / 64, TKN / 128, 8), 256, DSM4, s0>>>(
        attout, w_proj, nullptr, tok2, TKN, DIM, DIM, 0, 0);
    cudaEventRecord(g_sf.e_proj, s0);

    // s2: init_out in parallel
    cudaStreamWaitEvent(s2, g_sf.e_proj, 0);
    init_k<<<(TKN * DIM + 255) / 256, 256, 0, s2>>>(tok2, b_fc2, out, TKN * DIM, DIM);
    cudaEventRecord(g_sf.e_outi, s2);

    // s0: LN2 -> fc1 (fused bias+gelu) -> fc2
    ln_k<<<TKN, 128, 0, s0>>>(tok2, ln2_g, ln2_b, xbuf);
    mma_gemm_t<4><<<dim3((4 * DIM) / 64, TKN / 128, 1), 256, DSM4, s0>>>(
        xbuf, w_fc1, b_fc1, ff, TKN, 4 * DIM, DIM, 0, 1);
    cudaStreamWaitEvent(s0, g_sf.e_outi, 0);
    mma_gemm_t<4><<<dim3(DIM / 64, TKN / 128, 16), 256, DSM4, s0>>>(
        ff, w_fc2, nullptr, out, TKN, DIM, 4 * DIM, 0, 0);
}